// round 1
// baseline (speedup 1.0000x reference)
#include <cuda_runtime.h>

#define N_NODES 100000
#define N_EDGES 1600000
#define IN_CH 128
#define ED_CH 32
#define HEADS 4
#define CH 32
#define HC 128
#define NEG_SLOPE 0.2f

// ---------------- scratch (no runtime allocation allowed) ----------------
__device__ float g_xh[N_NODES * HC];          // 51.2 MB  x @ W, [N,H,C]
__device__ float g_asrc[N_NODES * HEADS];
__device__ float g_adst[N_NODES * HEADS];
__device__ float g_weff[ED_CH * HEADS];       // [32,4] folded W_edge@att_edge
__device__ float g_logit[N_EDGES * HEADS];    // 25.6 MB logits -> expv (in place)
__device__ int   g_maxk[N_NODES * HEADS];     // orderable-int encoded max
__device__ float g_denom[N_NODES * HEADS];

// ---------------- init: zero out + denom, set maxk = INT_MIN ----------------
__global__ void k_init(float* __restrict__ out) {
    int i = blockIdx.x * blockDim.x + threadIdx.x;
    if (i < N_NODES * CH) out[i] = 0.f;
    if (i < N_NODES * HEADS) { g_maxk[i] = 0x80000000; g_denom[i] = 0.f; }
}

// ---------------- w_eff[d,h] = sum_c W_edge[d, h*C+c] * att_edge[h,c] -------
__global__ void k_weff(const float* __restrict__ W_edge,
                       const float* __restrict__ att_edge) {
    int t = threadIdx.x;           // 128 threads
    int d = t >> 2, h = t & 3;
    float s = 0.f;
    #pragma unroll
    for (int c = 0; c < CH; c++)
        s += W_edge[d * HC + h * CH + c] * att_edge[h * CH + c];
    g_weff[d * HEADS + h] = s;
}

// ---------------- xh = x @ W  (M=100000, N=128, K=128) ----------------------
// BM=64, BN=128, BK=16, 256 threads, each thread 8x4 microtile.
__global__ __launch_bounds__(256) void k_gemm(const float* __restrict__ x,
                                              const float* __restrict__ W) {
    __shared__ float sA[16][65];     // [k][m], pad to avoid store conflicts
    __shared__ float sB[16][128];    // [k][n]
    int tid = threadIdx.x;
    int m0  = blockIdx.x * 64;
    int tx  = tid & 31;              // col group (4 cols)
    int ty  = tid >> 5;              // row group (8 rows)
    float acc[8][4] = {};

    int lr = tid >> 2;               // A-load row 0..63
    int lc = (tid & 3) * 4;          // A-load col chunk

    for (int k0 = 0; k0 < IN_CH; k0 += 16) {
        float4 av = make_float4(0.f, 0.f, 0.f, 0.f);
        int gr = m0 + lr;
        if (gr < N_NODES) av = *(const float4*)(x + (size_t)gr * IN_CH + k0 + lc);
        sA[lc + 0][lr] = av.x; sA[lc + 1][lr] = av.y;
        sA[lc + 2][lr] = av.z; sA[lc + 3][lr] = av.w;
        #pragma unroll
        for (int j = 0; j < 2; j++) {
            int lin = tid + j * 256;
            int br = lin >> 5;            // 0..15
            int bc = (lin & 31) * 4;
            *(float4*)&sB[br][bc] = *(const float4*)(W + (size_t)(k0 + br) * HC + bc);
        }
        __syncthreads();
        #pragma unroll
        for (int k = 0; k < 16; k++) {
            float4 b = *(const float4*)&sB[k][tx * 4];
            float a[8];
            #pragma unroll
            for (int i = 0; i < 8; i++) a[i] = sA[k][ty * 8 + i];
            #pragma unroll
            for (int i = 0; i < 8; i++) {
                acc[i][0] += a[i] * b.x; acc[i][1] += a[i] * b.y;
                acc[i][2] += a[i] * b.z; acc[i][3] += a[i] * b.w;
            }
        }
        __syncthreads();
    }
    #pragma unroll
    for (int i = 0; i < 8; i++) {
        int gr = m0 + ty * 8 + i;
        if (gr < N_NODES)
            *(float4*)(g_xh + (size_t)gr * HC + tx * 4) =
                make_float4(acc[i][0], acc[i][1], acc[i][2], acc[i][3]);
    }
}

// ---------------- a_src/a_dst per node (warp per node) ----------------------
__global__ __launch_bounds__(256) void k_att(const float* __restrict__ att_src,
                                             const float* __restrict__ att_dst) {
    int n = blockIdx.x * 8 + (threadIdx.x >> 5);
    if (n >= N_NODES) return;
    int lane = threadIdx.x & 31;
    float s[4], d[4];
    #pragma unroll
    for (int h = 0; h < 4; h++) {
        float v = g_xh[(size_t)n * HC + h * CH + lane];
        s[h] = v * att_src[h * CH + lane];
        d[h] = v * att_dst[h * CH + lane];
    }
    #pragma unroll
    for (int o = 16; o; o >>= 1) {
        #pragma unroll
        for (int h = 0; h < 4; h++) {
            s[h] += __shfl_xor_sync(0xffffffffu, s[h], o);
            d[h] += __shfl_xor_sync(0xffffffffu, d[h], o);
        }
    }
    if (lane == 0) {
        #pragma unroll
        for (int h = 0; h < 4; h++) {
            g_asrc[n * HEADS + h] = s[h];
            g_adst[n * HEADS + h] = d[h];
        }
    }
}

// ---------------- pass A: logits + leaky_relu + segment max (warp/edge) -----
__global__ __launch_bounds__(256) void k_logits(const int* __restrict__ ei,
                                                const float* __restrict__ ea) {
    int e = blockIdx.x * 8 + (threadIdx.x >> 5);
    if (e >= N_EDGES) return;
    int lane = threadIdx.x & 31;
    float v = ea[(size_t)e * ED_CH + lane];
    float4 w = *(const float4*)(g_weff + lane * 4);
    float s0 = v * w.x, s1 = v * w.y, s2 = v * w.z, s3 = v * w.w;
    #pragma unroll
    for (int o = 16; o; o >>= 1) {
        s0 += __shfl_xor_sync(0xffffffffu, s0, o);
        s1 += __shfl_xor_sync(0xffffffffu, s1, o);
        s2 += __shfl_xor_sync(0xffffffffu, s2, o);
        s3 += __shfl_xor_sync(0xffffffffu, s3, o);
    }
    if (lane < 4) {
        int src = ei[e], dst = ei[N_EDGES + e];
        float ae = (lane == 0) ? s0 : (lane == 1) ? s1 : (lane == 2) ? s2 : s3;
        float lg = g_asrc[src * HEADS + lane] + g_adst[dst * HEADS + lane] + ae;
        lg = lg >= 0.f ? lg : NEG_SLOPE * lg;
        g_logit[(size_t)e * HEADS + lane] = lg;
        int key = __float_as_int(lg);
        key = key >= 0 ? key : key ^ 0x7fffffff;   // orderable-int encoding
        atomicMax(&g_maxk[dst * HEADS + lane], key);
    }
}

// ---------------- pass B: expv + segment sum --------------------------------
__global__ void k_exp(const int* __restrict__ ei) {
    int idx = blockIdx.x * blockDim.x + threadIdx.x;
    if (idx >= N_EDGES * HEADS) return;
    int e = idx >> 2, h = idx & 3;
    int dst = ei[N_EDGES + e];
    int key = g_maxk[dst * HEADS + h];
    float mx = __int_as_float(key >= 0 ? key : key ^ 0x7fffffff);
    float ev = __expf(g_logit[idx] - mx);
    g_logit[idx] = ev;                              // in-place: logits -> expv
    atomicAdd(&g_denom[dst * HEADS + h], ev);
}

// ---------------- pass C: aggregate, head-mean folded into scatter ----------
__global__ __launch_bounds__(256) void k_agg(const int* __restrict__ ei,
                                             float* __restrict__ out) {
    int e = blockIdx.x * 8 + (threadIdx.x >> 5);
    if (e >= N_EDGES) return;
    int lane = threadIdx.x & 31;
    int src = ei[e], dst = ei[N_EDGES + e];
    float al = 0.f;
    if (lane < 4)
        al = g_logit[(size_t)e * HEADS + lane] / g_denom[dst * HEADS + lane];
    float a0 = __shfl_sync(0xffffffffu, al, 0);
    float a1 = __shfl_sync(0xffffffffu, al, 1);
    float a2 = __shfl_sync(0xffffffffu, al, 2);
    float a3 = __shfl_sync(0xffffffffu, al, 3);
    const float* xr = g_xh + (size_t)src * HC;
    float m = xr[lane]      * a0 + xr[32 + lane] * a1 +
              xr[64 + lane] * a2 + xr[96 + lane] * a3;
    atomicAdd(out + (size_t)dst * CH + lane, 0.25f * m);   // mean over heads
}

// ---------------- final: + mean(gat_bias) + bias, relu ----------------------
__global__ void k_final(float* __restrict__ out,
                        const float* __restrict__ gat_bias,
                        const float* __restrict__ bias) {
    int i = blockIdx.x * blockDim.x + threadIdx.x;
    if (i >= N_NODES * CH) return;
    int c = i & 31;
    float gb = 0.25f * (gat_bias[c] + gat_bias[32 + c] +
                        gat_bias[64 + c] + gat_bias[96 + c]);
    float v = out[i] + gb + bias[c];
    out[i] = v > 0.f ? v : 0.f;
}

extern "C" void kernel_launch(void* const* d_in, const int* in_sizes, int n_in,
                              void* d_out, int out_size) {
    const float* x        = (const float*)d_in[0];
    const int*   ei       = (const int*)  d_in[1];
    const float* ea       = (const float*)d_in[2];
    const float* W        = (const float*)d_in[3];
    const float* att_src  = (const float*)d_in[4];
    const float* att_dst  = (const float*)d_in[5];
    const float* W_edge   = (const float*)d_in[6];
    const float* att_edge = (const float*)d_in[7];
    const float* gat_bias = (const float*)d_in[8];
    const float* bias     = (const float*)d_in[9];
    float* out = (float*)d_out;

    k_init  <<<(N_NODES * CH + 255) / 256, 256>>>(out);
    k_weff  <<<1, 128>>>(W_edge, att_edge);
    k_gemm  <<<(N_NODES + 63) / 64, 256>>>(x, W);
    k_att   <<<(N_NODES + 7) / 8, 256>>>(att_src, att_dst);
    k_logits<<<(N_EDGES + 7) / 8, 256>>>(ei, ea);
    k_exp   <<<(N_EDGES * HEADS + 255) / 256, 256>>>(ei);
    k_agg   <<<(N_EDGES + 7) / 8, 256>>>(ei, out);
    k_final <<<(N_NODES * CH + 255) / 256, 256>>>(out, gat_bias, bias);
}

// round 2
// speedup vs baseline: 1.3665x; 1.3665x over previous
#include <cuda_runtime.h>

#define N_NODES 100000
#define N_EDGES 1600000
#define IN_CH 128
#define ED_CH 32
#define HEADS 4
#define CH 32
#define HC 128
#define NEG_SLOPE 0.2f
#define SCAN_BLK 1024
#define N_SCAN_BLKS ((N_NODES + SCAN_BLK - 1) / SCAN_BLK)   // 98

// ---------------- scratch (no runtime allocation allowed) ----------------
__device__ float g_xh[N_NODES * HC];            // 51.2 MB  x @ W, [N,H,C]
__device__ float g_asrc[N_NODES * HEADS];
__device__ float g_adst[N_NODES * HEADS];
__device__ float g_weff[ED_CH * HEADS];         // folded W_edge @ att_edge
__device__ float g_expv[N_EDGES * HEADS];       // exp(leaky(logit)) per edge/head
__device__ float g_ev_perm[N_EDGES * HEADS];    // expv permuted by dst
__device__ int   g_src_perm[N_EDGES];           // src permuted by dst
__device__ int   g_count[N_NODES];
__device__ int   g_rowptr[N_NODES + 1];
__device__ int   g_cursor[N_NODES];
__device__ int   g_bsum[N_SCAN_BLKS];
__device__ int   g_boff[N_SCAN_BLKS];

// ---------------- init: zero edge counts ------------------------------------
__global__ void k_init() {
    int i = blockIdx.x * blockDim.x + threadIdx.x;
    if (i < N_NODES) g_count[i] = 0;
}

// ---------------- w_eff[d,h] = sum_c W_edge[d, h*C+c] * att_edge[h,c] -------
__global__ void k_weff(const float* __restrict__ W_edge,
                       const float* __restrict__ att_edge) {
    int t = threadIdx.x;           // 128 threads
    int d = t >> 2, h = t & 3;
    float s = 0.f;
    #pragma unroll
    for (int c = 0; c < CH; c++)
        s += W_edge[d * HC + h * CH + c] * att_edge[h * CH + c];
    g_weff[d * HEADS + h] = s;
}

// ---------------- xh = x @ W + fused a_src/a_dst epilogue -------------------
// BM=64, BN=128(full), BK=16, 256 threads, 8x4 microtile per thread.
__global__ __launch_bounds__(256) void k_gemm(const float* __restrict__ x,
                                              const float* __restrict__ W,
                                              const float* __restrict__ att_src,
                                              const float* __restrict__ att_dst) {
    __shared__ float sA[16][65];
    __shared__ float sB[16][128];
    int tid = threadIdx.x;
    int m0  = blockIdx.x * 64;
    int tx  = tid & 31;
    int ty  = tid >> 5;
    float acc[8][4] = {};

    int lr = tid >> 2;
    int lc = (tid & 3) * 4;

    for (int k0 = 0; k0 < IN_CH; k0 += 16) {
        float4 av = make_float4(0.f, 0.f, 0.f, 0.f);
        int gr = m0 + lr;
        if (gr < N_NODES) av = *(const float4*)(x + (size_t)gr * IN_CH + k0 + lc);
        sA[lc + 0][lr] = av.x; sA[lc + 1][lr] = av.y;
        sA[lc + 2][lr] = av.z; sA[lc + 3][lr] = av.w;
        #pragma unroll
        for (int j = 0; j < 2; j++) {
            int lin = tid + j * 256;
            int br = lin >> 5;
            int bc = (lin & 31) * 4;
            *(float4*)&sB[br][bc] = *(const float4*)(W + (size_t)(k0 + br) * HC + bc);
        }
        __syncthreads();
        #pragma unroll
        for (int k = 0; k < 16; k++) {
            float4 b = *(const float4*)&sB[k][tx * 4];
            float a[8];
            #pragma unroll
            for (int i = 0; i < 8; i++) a[i] = sA[k][ty * 8 + i];
            #pragma unroll
            for (int i = 0; i < 8; i++) {
                acc[i][0] += a[i] * b.x; acc[i][1] += a[i] * b.y;
                acc[i][2] += a[i] * b.z; acc[i][3] += a[i] * b.w;
            }
        }
        __syncthreads();
    }
    // store xh
    #pragma unroll
    for (int i = 0; i < 8; i++) {
        int gr = m0 + ty * 8 + i;
        if (gr < N_NODES)
            *(float4*)(g_xh + (size_t)gr * HC + tx * 4) =
                make_float4(acc[i][0], acc[i][1], acc[i][2], acc[i][3]);
    }
    // fused attention-coefficient epilogue: reduce over this thread's 4 cols,
    // then across the 8 lanes that share one head (tx groups of 8).
    float4 as4 = *(const float4*)(att_src + tx * 4);
    float4 ad4 = *(const float4*)(att_dst + tx * 4);
    #pragma unroll
    for (int i = 0; i < 8; i++) {
        float s = acc[i][0] * as4.x + acc[i][1] * as4.y +
                  acc[i][2] * as4.z + acc[i][3] * as4.w;
        float d = acc[i][0] * ad4.x + acc[i][1] * ad4.y +
                  acc[i][2] * ad4.z + acc[i][3] * ad4.w;
        #pragma unroll
        for (int o = 1; o < 8; o <<= 1) {
            s += __shfl_xor_sync(0xffffffffu, s, o);
            d += __shfl_xor_sync(0xffffffffu, d, o);
        }
        if ((tx & 7) == 0) {
            int gr = m0 + ty * 8 + i;
            if (gr < N_NODES) {
                int h = tx >> 3;
                g_asrc[gr * HEADS + h] = s;
                g_adst[gr * HEADS + h] = d;
            }
        }
    }
}

// ---------------- edge pass: logits -> leaky -> exp, + degree count ---------
__global__ __launch_bounds__(256) void k_edge(const int* __restrict__ ei,
                                              const float* __restrict__ ea) {
    int e = blockIdx.x * 8 + (threadIdx.x >> 5);
    if (e >= N_EDGES) return;
    int lane = threadIdx.x & 31;
    float v = ea[(size_t)e * ED_CH + lane];
    float4 w = *(const float4*)(g_weff + lane * 4);
    float s0 = v * w.x, s1 = v * w.y, s2 = v * w.z, s3 = v * w.w;
    #pragma unroll
    for (int o = 16; o; o >>= 1) {
        s0 += __shfl_xor_sync(0xffffffffu, s0, o);
        s1 += __shfl_xor_sync(0xffffffffu, s1, o);
        s2 += __shfl_xor_sync(0xffffffffu, s2, o);
        s3 += __shfl_xor_sync(0xffffffffu, s3, o);
    }
    int src = __shfl_sync(0xffffffffu, lane == 0 ? 0 : 0, 0); // placeholder no-op
    if (lane < 4) {
        int s  = ei[e];
        int d  = ei[N_EDGES + e];
        float ae = (lane == 0) ? s0 : (lane == 1) ? s1 : (lane == 2) ? s2 : s3;
        float lg = g_asrc[s * HEADS + lane] + g_adst[d * HEADS + lane] + ae;
        lg = lg >= 0.f ? lg : NEG_SLOPE * lg;
        g_expv[(size_t)e * HEADS + lane] = __expf(lg);
        if (lane == 0) atomicAdd(&g_count[d], 1);
    }
    (void)src;
}

// ---------------- scan step 1: per-1024-block exclusive scan ---------------
__global__ __launch_bounds__(256) void k_scan1() {
    int b = blockIdx.x;
    int base = b * SCAN_BLK;
    int tid = threadIdx.x;
    int lane = tid & 31, w = tid >> 5;
    int v[4], ts = 0;
    #pragma unroll
    for (int j = 0; j < 4; j++) {
        int idx = base + tid * 4 + j;
        v[j] = (idx < N_NODES) ? g_count[idx] : 0;
        ts += v[j];
    }
    int incl = ts;
    #pragma unroll
    for (int o = 1; o < 32; o <<= 1) {
        int t = __shfl_up_sync(0xffffffffu, incl, o);
        if (lane >= o) incl += t;
    }
    __shared__ int wsum[8];
    if (lane == 31) wsum[w] = incl;
    __syncthreads();
    if (w == 0 && lane < 8) {
        int t = wsum[lane];
        #pragma unroll
        for (int o = 1; o < 8; o <<= 1) {
            int u = __shfl_up_sync(0xffu, t, o);
            if (lane >= o) t += u;
        }
        wsum[lane] = t;
    }
    __syncthreads();
    int excl = incl - ts + (w > 0 ? wsum[w - 1] : 0);
    int run = excl;
    #pragma unroll
    for (int j = 0; j < 4; j++) {
        int idx = base + tid * 4 + j;
        if (idx < N_NODES) g_rowptr[idx] = run;
        run += v[j];
    }
    if (tid == 0) g_bsum[b] = 0;   // overwritten below; keep deterministic
    __syncthreads();
    if (tid == 255) g_bsum[b] = wsum[7];
}

// ---------------- scan step 2: scan the 98 block sums ----------------------
__global__ void k_scan2() {
    if (threadIdx.x == 0) {
        int run = 0;
        for (int b = 0; b < N_SCAN_BLKS; b++) { g_boff[b] = run; run += g_bsum[b]; }
        g_rowptr[N_NODES] = N_EDGES;
    }
}

// ---------------- scan step 3: add offsets, init cursors -------------------
__global__ void k_scan3() {
    int i = blockIdx.x * blockDim.x + threadIdx.x;
    if (i >= N_NODES) return;
    int r = g_rowptr[i] + g_boff[i >> 10];
    g_rowptr[i] = r;
    g_cursor[i] = r;
}

// ---------------- scatter: build dst-grouped edge arrays -------------------
__global__ __launch_bounds__(256) void k_scatter(const int* __restrict__ ei) {
    int e = blockIdx.x * blockDim.x + threadIdx.x;
    if (e >= N_EDGES) return;
    int src = ei[e];
    int dst = ei[N_EDGES + e];
    int pos = atomicAdd(&g_cursor[dst], 1);
    g_src_perm[pos] = src;
    float4 ev = *(const float4*)(g_expv + (size_t)e * HEADS);
    *(float4*)(g_ev_perm + (size_t)pos * HEADS) = ev;
}

// ---------------- aggregate: warp per node, no atomics, fused epilogue -----
__global__ __launch_bounds__(256) void k_agg(float* __restrict__ out,
                                             const float* __restrict__ gat_bias,
                                             const float* __restrict__ bias) {
    int n = blockIdx.x * 8 + (threadIdx.x >> 5);
    if (n >= N_NODES) return;
    int lane = threadIdx.x & 31;
    int beg = g_rowptr[n];
    int end = g_rowptr[n + 1];
    float a0 = 0.f, a1 = 0.f, a2 = 0.f, a3 = 0.f;
    float d0 = 0.f, d1 = 0.f, d2 = 0.f, d3 = 0.f;
    #pragma unroll 2
    for (int idx = beg; idx < end; idx++) {
        int src = g_src_perm[idx];
        float4 ev = *(const float4*)(g_ev_perm + (size_t)idx * HEADS);
        const float* xr = g_xh + (size_t)src * HC;
        a0 += ev.x * xr[lane];
        a1 += ev.y * xr[32 + lane];
        a2 += ev.z * xr[64 + lane];
        a3 += ev.w * xr[96 + lane];
        d0 += ev.x; d1 += ev.y; d2 += ev.z; d3 += ev.w;
    }
    float m = 0.f;
    if (d0 > 0.f) m += a0 / d0;
    if (d1 > 0.f) m += a1 / d1;
    if (d2 > 0.f) m += a2 / d2;
    if (d3 > 0.f) m += a3 / d3;
    float gb = 0.25f * (gat_bias[lane] + gat_bias[32 + lane] +
                        gat_bias[64 + lane] + gat_bias[96 + lane]);
    float v = 0.25f * m + gb + bias[lane];
    out[(size_t)n * CH + lane] = v > 0.f ? v : 0.f;
}

extern "C" void kernel_launch(void* const* d_in, const int* in_sizes, int n_in,
                              void* d_out, int out_size) {
    const float* x        = (const float*)d_in[0];
    const int*   ei       = (const int*)  d_in[1];
    const float* ea       = (const float*)d_in[2];
    const float* W        = (const float*)d_in[3];
    const float* att_src  = (const float*)d_in[4];
    const float* att_dst  = (const float*)d_in[5];
    const float* W_edge   = (const float*)d_in[6];
    const float* att_edge = (const float*)d_in[7];
    const float* gat_bias = (const float*)d_in[8];
    const float* bias     = (const float*)d_in[9];
    float* out = (float*)d_out;

    k_init   <<<(N_NODES + 255) / 256, 256>>>();
    k_weff   <<<1, 128>>>(W_edge, att_edge);
    k_gemm   <<<(N_NODES + 63) / 64, 256>>>(x, W, att_src, att_dst);
    k_edge   <<<(N_EDGES + 7) / 8, 256>>>(ei, ea);
    k_scan1  <<<N_SCAN_BLKS, 256>>>();
    k_scan2  <<<1, 32>>>();
    k_scan3  <<<(N_NODES + 255) / 256, 256>>>();
    k_scatter<<<(N_EDGES + 255) / 256, 256>>>(ei);
    k_agg    <<<(N_NODES + 7) / 8, 256>>>(out, gat_bias, bias);
}

// round 3
// speedup vs baseline: 2.2300x; 1.6319x over previous
#include <cuda_runtime.h>

#define N_NODES 100000
#define N_EDGES 1600000
#define IN_CH 128
#define ED_CH 32
#define HEADS 4
#define CH 32
#define HC 128
#define NEG_SLOPE 0.2f
#define SCAN_BLK 1024
#define N_SCAN_BLKS ((N_NODES + SCAN_BLK - 1) / SCAN_BLK)   // 98

// ---------------- scratch (no runtime allocation allowed) ----------------
__device__ float g_xh[N_NODES * HC];            // 51.2 MB  x @ W, [N,H,C]
__device__ float g_asrc[N_NODES * HEADS];
__device__ float g_adst[N_NODES * HEADS];
__device__ float g_weff[ED_CH * HEADS];         // folded W_edge @ att_edge
__device__ float g_ev_perm[N_EDGES * HEADS];    // expv permuted by dst
__device__ int   g_src_perm[N_EDGES];           // src permuted by dst
__device__ int   g_count[N_NODES];
__device__ int   g_rowptr[N_NODES + 1];
__device__ int   g_cursor[N_NODES];
__device__ int   g_bsum[N_SCAN_BLKS];
__device__ int   g_boff[N_SCAN_BLKS];

// ---------------- init: zero edge counts ------------------------------------
__global__ void k_init() {
    int i = blockIdx.x * blockDim.x + threadIdx.x;
    if (i < N_NODES) g_count[i] = 0;
}

// ---------------- w_eff[d,h] = sum_c W_edge[d, h*C+c] * att_edge[h,c] -------
__global__ void k_weff(const float* __restrict__ W_edge,
                       const float* __restrict__ att_edge) {
    int t = threadIdx.x;           // 128 threads
    int d = t >> 2, h = t & 3;
    float s = 0.f;
    #pragma unroll
    for (int c = 0; c < CH; c++)
        s += W_edge[d * HC + h * CH + c] * att_edge[h * CH + c];
    g_weff[d * HEADS + h] = s;
}

// ---------------- degree count (thread per edge) ----------------------------
__global__ void k_count(const int* __restrict__ ei) {
    int e = blockIdx.x * blockDim.x + threadIdx.x;
    if (e < N_EDGES) atomicAdd(&g_count[ei[N_EDGES + e]], 1);
}

// ---------------- xh = x @ W + fused a_src/a_dst epilogue -------------------
__global__ __launch_bounds__(256) void k_gemm(const float* __restrict__ x,
                                              const float* __restrict__ W,
                                              const float* __restrict__ att_src,
                                              const float* __restrict__ att_dst) {
    __shared__ float sA[16][65];
    __shared__ float sB[16][128];
    int tid = threadIdx.x;
    int m0  = blockIdx.x * 64;
    int tx  = tid & 31;
    int ty  = tid >> 5;
    float acc[8][4] = {};

    int lr = tid >> 2;
    int lc = (tid & 3) * 4;

    for (int k0 = 0; k0 < IN_CH; k0 += 16) {
        float4 av = make_float4(0.f, 0.f, 0.f, 0.f);
        int gr = m0 + lr;
        if (gr < N_NODES) av = *(const float4*)(x + (size_t)gr * IN_CH + k0 + lc);
        sA[lc + 0][lr] = av.x; sA[lc + 1][lr] = av.y;
        sA[lc + 2][lr] = av.z; sA[lc + 3][lr] = av.w;
        #pragma unroll
        for (int j = 0; j < 2; j++) {
            int lin = tid + j * 256;
            int br = lin >> 5;
            int bc = (lin & 31) * 4;
            *(float4*)&sB[br][bc] = *(const float4*)(W + (size_t)(k0 + br) * HC + bc);
        }
        __syncthreads();
        #pragma unroll
        for (int k = 0; k < 16; k++) {
            float4 b = *(const float4*)&sB[k][tx * 4];
            float a[8];
            #pragma unroll
            for (int i = 0; i < 8; i++) a[i] = sA[k][ty * 8 + i];
            #pragma unroll
            for (int i = 0; i < 8; i++) {
                acc[i][0] += a[i] * b.x; acc[i][1] += a[i] * b.y;
                acc[i][2] += a[i] * b.z; acc[i][3] += a[i] * b.w;
            }
        }
        __syncthreads();
    }
    #pragma unroll
    for (int i = 0; i < 8; i++) {
        int gr = m0 + ty * 8 + i;
        if (gr < N_NODES)
            *(float4*)(g_xh + (size_t)gr * HC + tx * 4) =
                make_float4(acc[i][0], acc[i][1], acc[i][2], acc[i][3]);
    }
    float4 as4 = *(const float4*)(att_src + tx * 4);
    float4 ad4 = *(const float4*)(att_dst + tx * 4);
    #pragma unroll
    for (int i = 0; i < 8; i++) {
        float s = acc[i][0] * as4.x + acc[i][1] * as4.y +
                  acc[i][2] * as4.z + acc[i][3] * as4.w;
        float d = acc[i][0] * ad4.x + acc[i][1] * ad4.y +
                  acc[i][2] * ad4.z + acc[i][3] * ad4.w;
        #pragma unroll
        for (int o = 1; o < 8; o <<= 1) {
            s += __shfl_xor_sync(0xffffffffu, s, o);
            d += __shfl_xor_sync(0xffffffffu, d, o);
        }
        if ((tx & 7) == 0) {
            int gr = m0 + ty * 8 + i;
            if (gr < N_NODES) {
                int h = tx >> 3;
                g_asrc[gr * HEADS + h] = s;
                g_adst[gr * HEADS + h] = d;
            }
        }
    }
}

// ---------------- scan step 1: per-1024-block exclusive scan ---------------
__global__ __launch_bounds__(256) void k_scan1() {
    int b = blockIdx.x;
    int base = b * SCAN_BLK;
    int tid = threadIdx.x;
    int lane = tid & 31, w = tid >> 5;
    int v[4], ts = 0;
    #pragma unroll
    for (int j = 0; j < 4; j++) {
        int idx = base + tid * 4 + j;
        v[j] = (idx < N_NODES) ? g_count[idx] : 0;
        ts += v[j];
    }
    int incl = ts;
    #pragma unroll
    for (int o = 1; o < 32; o <<= 1) {
        int t = __shfl_up_sync(0xffffffffu, incl, o);
        if (lane >= o) incl += t;
    }
    __shared__ int wsum[8];
    if (lane == 31) wsum[w] = incl;
    __syncthreads();
    if (w == 0 && lane < 8) {
        int t = wsum[lane];
        #pragma unroll
        for (int o = 1; o < 8; o <<= 1) {
            int u = __shfl_up_sync(0xffu, t, o);
            if (lane >= o) t += u;
        }
        wsum[lane] = t;
    }
    __syncthreads();
    int excl = incl - ts + (w > 0 ? wsum[w - 1] : 0);
    int run = excl;
    #pragma unroll
    for (int j = 0; j < 4; j++) {
        int idx = base + tid * 4 + j;
        if (idx < N_NODES) g_rowptr[idx] = run;
        run += v[j];
    }
    __syncthreads();
    if (tid == 255) g_bsum[b] = wsum[7];
}

// ---------------- scan step 2: scan the 98 block sums ----------------------
__global__ void k_scan2() {
    if (threadIdx.x == 0) {
        int run = 0;
        for (int b = 0; b < N_SCAN_BLKS; b++) { g_boff[b] = run; run += g_bsum[b]; }
        g_rowptr[N_NODES] = N_EDGES;
    }
}

// ---------------- scan step 3: add offsets, init cursors -------------------
__global__ void k_scan3() {
    int i = blockIdx.x * blockDim.x + threadIdx.x;
    if (i >= N_NODES) return;
    int r = g_rowptr[i] + g_boff[i >> 10];
    g_rowptr[i] = r;
    g_cursor[i] = r;
}

// ---------------- fused edge pass: logits->exp + CSR scatter ---------------
// 256 threads = 256 edges per block; edge rows staged coalesced into smem.
__global__ __launch_bounds__(256) void k_edge_scatter(const int* __restrict__ ei,
                                                      const float* __restrict__ ea) {
    __shared__ float sEA[256][33];    // padded: row reads conflict-free
    __shared__ float4 sW[32];         // w_eff rows as float4 (4 heads)
    int tid = threadIdx.x;
    int e0  = blockIdx.x * 256;

    if (tid < 32) sW[tid] = *(const float4*)(g_weff + tid * 4);

    // stage 256x32 floats (32KB) coalesced: 2048 float4, 8 per thread
    const float4* gsrc = (const float4*)(ea + (size_t)e0 * ED_CH);
    #pragma unroll
    for (int k = 0; k < 8; k++) {
        int idx = tid + k * 256;              // float4 index
        float4 v = gsrc[idx];
        int row = idx >> 3;
        int col = (idx & 7) * 4;
        sEA[row][col + 0] = v.x; sEA[row][col + 1] = v.y;
        sEA[row][col + 2] = v.z; sEA[row][col + 3] = v.w;
    }
    __syncthreads();

    int e = e0 + tid;
    float s0 = 0.f, s1 = 0.f, s2 = 0.f, s3 = 0.f;
    #pragma unroll
    for (int d = 0; d < 32; d++) {
        float v = sEA[tid][d];
        float4 w = sW[d];
        s0 += v * w.x; s1 += v * w.y; s2 += v * w.z; s3 += v * w.w;
    }
    int src = ei[e];
    int dst = ei[N_EDGES + e];
    float4 as = *(const float4*)(g_asrc + src * HEADS);
    float4 ad = *(const float4*)(g_adst + dst * HEADS);
    float l0 = as.x + ad.x + s0;
    float l1 = as.y + ad.y + s1;
    float l2 = as.z + ad.z + s2;
    float l3 = as.w + ad.w + s3;
    l0 = l0 >= 0.f ? l0 : NEG_SLOPE * l0;
    l1 = l1 >= 0.f ? l1 : NEG_SLOPE * l1;
    l2 = l2 >= 0.f ? l2 : NEG_SLOPE * l2;
    l3 = l3 >= 0.f ? l3 : NEG_SLOPE * l3;
    float4 ev = make_float4(__expf(l0), __expf(l1), __expf(l2), __expf(l3));
    int pos = atomicAdd(&g_cursor[dst], 1);
    g_src_perm[pos] = src;
    *(float4*)(g_ev_perm + (size_t)pos * HEADS) = ev;
}

// ---------------- aggregate: warp per node, no atomics, fused epilogue -----
__global__ __launch_bounds__(256) void k_agg(float* __restrict__ out,
                                             const float* __restrict__ gat_bias,
                                             const float* __restrict__ bias) {
    int n = blockIdx.x * 8 + (threadIdx.x >> 5);
    if (n >= N_NODES) return;
    int lane = threadIdx.x & 31;
    int beg = g_rowptr[n];
    int end = g_rowptr[n + 1];
    float a0 = 0.f, a1 = 0.f, a2 = 0.f, a3 = 0.f;
    float d0 = 0.f, d1 = 0.f, d2 = 0.f, d3 = 0.f;
    #pragma unroll 2
    for (int idx = beg; idx < end; idx++) {
        int src = g_src_perm[idx];
        float4 ev = *(const float4*)(g_ev_perm + (size_t)idx * HEADS);
        const float* xr = g_xh + (size_t)src * HC;
        a0 += ev.x * xr[lane];
        a1 += ev.y * xr[32 + lane];
        a2 += ev.z * xr[64 + lane];
        a3 += ev.w * xr[96 + lane];
        d0 += ev.x; d1 += ev.y; d2 += ev.z; d3 += ev.w;
    }
    float m = 0.f;
    if (d0 > 0.f) m += a0 / d0;
    if (d1 > 0.f) m += a1 / d1;
    if (d2 > 0.f) m += a2 / d2;
    if (d3 > 0.f) m += a3 / d3;
    float gb = 0.25f * (gat_bias[lane] + gat_bias[32 + lane] +
                        gat_bias[64 + lane] + gat_bias[96 + lane]);
    float v = 0.25f * m + gb + bias[lane];
    out[(size_t)n * CH + lane] = v > 0.f ? v : 0.f;
}

extern "C" void kernel_launch(void* const* d_in, const int* in_sizes, int n_in,
                              void* d_out, int out_size) {
    const float* x        = (const float*)d_in[0];
    const int*   ei       = (const int*)  d_in[1];
    const float* ea       = (const float*)d_in[2];
    const float* W        = (const float*)d_in[3];
    const float* att_src  = (const float*)d_in[4];
    const float* att_dst  = (const float*)d_in[5];
    const float* W_edge   = (const float*)d_in[6];
    const float* att_edge = (const float*)d_in[7];
    const float* gat_bias = (const float*)d_in[8];
    const float* bias     = (const float*)d_in[9];
    float* out = (float*)d_out;

    k_init        <<<(N_NODES + 255) / 256, 256>>>();
    k_weff        <<<1, 128>>>(W_edge, att_edge);
    k_count       <<<(N_EDGES + 255) / 256, 256>>>(ei);
    k_gemm        <<<(N_NODES + 63) / 64, 256>>>(x, W, att_src, att_dst);
    k_scan1       <<<N_SCAN_BLKS, 256>>>();
    k_scan2       <<<1, 32>>>();
    k_scan3       <<<(N_NODES + 255) / 256, 256>>>();
    k_edge_scatter<<<N_EDGES / 256, 256>>>(ei, ea);
    k_agg         <<<(N_NODES + 7) / 8, 256>>>(out, gat_bias, bias);
}

// round 4
// speedup vs baseline: 2.5588x; 1.1474x over previous
#include <cuda_runtime.h>

#define N_NODES 100000
#define N_EDGES 1600000
#define IN_CH 128
#define ED_CH 32
#define HEADS 4
#define CH 32
#define HC 128
#define NEG_SLOPE 0.2f
#define SCAN_BLK 1024
#define N_SCAN_BLKS ((N_NODES + SCAN_BLK - 1) / SCAN_BLK)   // 98

// ---------------- scratch (no runtime allocation allowed) ----------------
__device__ float g_xh[N_NODES * HC];            // 51.2 MB  x @ W, [N,H,C]
__device__ float g_asrc[N_NODES * HEADS];
__device__ float g_adst[N_NODES * HEADS];
__device__ float g_weff[ED_CH * HEADS];         // folded W_edge @ att_edge
__device__ uint2 g_Wp[16 * 16 * 32];            // W packed as tf32 B-fragments
__device__ float g_ev_perm[N_EDGES * HEADS];    // expv permuted by dst
__device__ int   g_src_perm[N_EDGES];           // src permuted by dst
__device__ int   g_count[N_NODES];
__device__ int   g_rowptr[N_NODES + 1];
__device__ int   g_cursor[N_NODES];
__device__ int   g_bsum[N_SCAN_BLKS];
__device__ int   g_boff[N_SCAN_BLKS];

__device__ __forceinline__ unsigned tf32r(float f) {
    unsigned r;
    asm("cvt.rna.tf32.f32 %0, %1;" : "=r"(r) : "f"(f));
    return r;
}

__device__ __forceinline__ void mma_tf32(float c[4], unsigned a0, unsigned a1,
                                         unsigned a2, unsigned a3,
                                         unsigned b0, unsigned b1) {
    asm volatile(
        "mma.sync.aligned.m16n8k8.row.col.f32.tf32.tf32.f32 "
        "{%0,%1,%2,%3},{%4,%5,%6,%7},{%8,%9},{%0,%1,%2,%3};"
        : "+f"(c[0]), "+f"(c[1]), "+f"(c[2]), "+f"(c[3])
        : "r"(a0), "r"(a1), "r"(a2), "r"(a3), "r"(b0), "r"(b1));
}

// ---------------- init: zero edge counts ------------------------------------
__global__ void k_init() {
    int i = blockIdx.x * blockDim.x + threadIdx.x;
    if (i < N_NODES) g_count[i] = 0;
}

// ---------------- w_eff[d,h] = sum_c W_edge[d, h*C+c] * att_edge[h,c] -------
__global__ void k_weff(const float* __restrict__ W_edge,
                       const float* __restrict__ att_edge) {
    int t = threadIdx.x;           // 128 threads
    int d = t >> 2, h = t & 3;
    float s = 0.f;
    #pragma unroll
    for (int c = 0; c < CH; c++)
        s += W_edge[d * HC + h * CH + c] * att_edge[h * CH + c];
    g_weff[d * HEADS + h] = s;
}

// ---------------- pack W into tf32 B-fragment order -------------------------
// Wp[kk][n][lane] = (tf32 W[8kk + lane%4][8n + lane/4], tf32 W[8kk + lane%4 + 4][...])
__global__ void k_wpack(const float* __restrict__ W) {
    int t = blockIdx.x * blockDim.x + threadIdx.x;   // 8192 threads
    if (t >= 16 * 16 * 32) return;
    int lane = t & 31;
    int n = (t >> 5) & 15;
    int kk = t >> 9;
    int krow = 8 * kk + (lane & 3);
    int col = 8 * n + (lane >> 2);
    uint2 b;
    b.x = tf32r(W[krow * HC + col]);
    b.y = tf32r(W[(krow + 4) * HC + col]);
    g_Wp[t] = b;
}

// ---------------- degree count (thread per edge) ----------------------------
__global__ void k_count(const int* __restrict__ ei) {
    int e = blockIdx.x * blockDim.x + threadIdx.x;
    if (e < N_EDGES) atomicAdd(&g_count[ei[N_EDGES + e]], 1);
}

// ---------------- xh = x @ W via tf32 mma + fused a_src/a_dst ---------------
// 256 threads = 8 warps; warp computes 16 rows x 128 cols. No smem, no syncs.
__global__ __launch_bounds__(256) void k_gemm(const float* __restrict__ x,
                                              const float* __restrict__ att_src,
                                              const float* __restrict__ att_dst) {
    int tid  = threadIdx.x;
    int warp = tid >> 5;
    int lane = tid & 31;
    int grp  = lane >> 2;      // 0..7 (row within fragment)
    int q    = lane & 3;       // quad id (col group)

    int r0  = blockIdx.x * 128 + warp * 16;
    int rlo = r0 + grp;
    int rhi = rlo + 8;
    int rloL = rlo < N_NODES ? rlo : N_NODES - 1;
    int rhiL = rhi < N_NODES ? rhi : N_NODES - 1;
    const float* xlo = x + (size_t)rloL * IN_CH;
    const float* xhi = x + (size_t)rhiL * IN_CH;

    float c[16][4];
    #pragma unroll
    for (int n = 0; n < 16; n++) { c[n][0] = c[n][1] = c[n][2] = c[n][3] = 0.f; }

    #pragma unroll
    for (int kk = 0; kk < 16; kk++) {
        int k0 = 8 * kk;
        unsigned a0 = tf32r(__ldg(xlo + k0 + q));
        unsigned a1 = tf32r(__ldg(xhi + k0 + q));
        unsigned a2 = tf32r(__ldg(xlo + k0 + q + 4));
        unsigned a3 = tf32r(__ldg(xhi + k0 + q + 4));
        const uint2* wp = g_Wp + (size_t)kk * 16 * 32 + lane;
        #pragma unroll
        for (int n = 0; n < 16; n++) {
            uint2 b = __ldg(wp + n * 32);
            mma_tf32(c[n], a0, a1, a2, a3, b.x, b.y);
        }
    }

    // epilogue: store xh + accumulate per-head attention dots
    float sl[4] = {0.f, 0.f, 0.f, 0.f}, dl[4] = {0.f, 0.f, 0.f, 0.f};
    float sh[4] = {0.f, 0.f, 0.f, 0.f}, dh[4] = {0.f, 0.f, 0.f, 0.f};
    bool wlo = rlo < N_NODES, whi = rhi < N_NODES;
    #pragma unroll
    for (int n = 0; n < 16; n++) {
        int col = 8 * n + 2 * q;
        int h = n >> 2;
        float as0 = __ldg(att_src + col), as1 = __ldg(att_src + col + 1);
        float ad0 = __ldg(att_dst + col), ad1 = __ldg(att_dst + col + 1);
        if (wlo)
            *(float2*)(g_xh + (size_t)rlo * HC + col) = make_float2(c[n][0], c[n][1]);
        if (whi)
            *(float2*)(g_xh + (size_t)rhi * HC + col) = make_float2(c[n][2], c[n][3]);
        sl[h] += c[n][0] * as0 + c[n][1] * as1;
        dl[h] += c[n][0] * ad0 + c[n][1] * ad1;
        sh[h] += c[n][2] * as0 + c[n][3] * as1;
        dh[h] += c[n][2] * ad0 + c[n][3] * ad1;
    }
    #pragma unroll
    for (int h = 0; h < 4; h++) {
        #pragma unroll
        for (int o = 1; o < 4; o <<= 1) {
            sl[h] += __shfl_xor_sync(0xffffffffu, sl[h], o);
            dl[h] += __shfl_xor_sync(0xffffffffu, dl[h], o);
            sh[h] += __shfl_xor_sync(0xffffffffu, sh[h], o);
            dh[h] += __shfl_xor_sync(0xffffffffu, dh[h], o);
        }
    }
    if (q == 0) {
        #pragma unroll
        for (int h = 0; h < 4; h++) {
            if (wlo) { g_asrc[rlo * HEADS + h] = sl[h]; g_adst[rlo * HEADS + h] = dl[h]; }
            if (whi) { g_asrc[rhi * HEADS + h] = sh[h]; g_adst[rhi * HEADS + h] = dh[h]; }
        }
    }
}

// ---------------- scan step 1: per-1024-block exclusive scan ---------------
__global__ __launch_bounds__(256) void k_scan1() {
    int b = blockIdx.x;
    int base = b * SCAN_BLK;
    int tid = threadIdx.x;
    int lane = tid & 31, w = tid >> 5;
    int v[4], ts = 0;
    #pragma unroll
    for (int j = 0; j < 4; j++) {
        int idx = base + tid * 4 + j;
        v[j] = (idx < N_NODES) ? g_count[idx] : 0;
        ts += v[j];
    }
    int incl = ts;
    #pragma unroll
    for (int o = 1; o < 32; o <<= 1) {
        int t = __shfl_up_sync(0xffffffffu, incl, o);
        if (lane >= o) incl += t;
    }
    __shared__ int wsum[8];
    if (lane == 31) wsum[w] = incl;
    __syncthreads();
    if (w == 0 && lane < 8) {
        int t = wsum[lane];
        #pragma unroll
        for (int o = 1; o < 8; o <<= 1) {
            int u = __shfl_up_sync(0xffu, t, o);
            if (lane >= o) t += u;
        }
        wsum[lane] = t;
    }
    __syncthreads();
    int excl = incl - ts + (w > 0 ? wsum[w - 1] : 0);
    int run = excl;
    #pragma unroll
    for (int j = 0; j < 4; j++) {
        int idx = base + tid * 4 + j;
        if (idx < N_NODES) g_rowptr[idx] = run;
        run += v[j];
    }
    __syncthreads();
    if (tid == 255) g_bsum[b] = wsum[7];
}

// ---------------- scan step 2: scan the 98 block sums ----------------------
__global__ void k_scan2() {
    if (threadIdx.x == 0) {
        int run = 0;
        for (int b = 0; b < N_SCAN_BLKS; b++) { g_boff[b] = run; run += g_bsum[b]; }
        g_rowptr[N_NODES] = N_EDGES;
    }
}

// ---------------- scan step 3: add offsets, init cursors -------------------
__global__ void k_scan3() {
    int i = blockIdx.x * blockDim.x + threadIdx.x;
    if (i >= N_NODES) return;
    int r = g_rowptr[i] + g_boff[i >> 10];
    g_rowptr[i] = r;
    g_cursor[i] = r;
}

// ---------------- fused edge pass: logits->exp + CSR scatter ---------------
__global__ __launch_bounds__(256) void k_edge_scatter(const int* __restrict__ ei,
                                                      const float* __restrict__ ea) {
    __shared__ float sEA[256][33];
    __shared__ float4 sW[32];
    int tid = threadIdx.x;
    int e0  = blockIdx.x * 256;

    if (tid < 32) sW[tid] = *(const float4*)(g_weff + tid * 4);

    const float4* gsrc = (const float4*)(ea + (size_t)e0 * ED_CH);
    #pragma unroll
    for (int k = 0; k < 8; k++) {
        int idx = tid + k * 256;
        float4 v = gsrc[idx];
        int row = idx >> 3;
        int col = (idx & 7) * 4;
        sEA[row][col + 0] = v.x; sEA[row][col + 1] = v.y;
        sEA[row][col + 2] = v.z; sEA[row][col + 3] = v.w;
    }
    __syncthreads();

    int e = e0 + tid;
    float s0 = 0.f, s1 = 0.f, s2 = 0.f, s3 = 0.f;
    #pragma unroll
    for (int d = 0; d < 32; d++) {
        float v = sEA[tid][d];
        float4 w = sW[d];
        s0 += v * w.x; s1 += v * w.y; s2 += v * w.z; s3 += v * w.w;
    }
    int src = ei[e];
    int dst = ei[N_EDGES + e];
    float4 as = *(const float4*)(g_asrc + src * HEADS);
    float4 ad = *(const float4*)(g_adst + dst * HEADS);
    float l0 = as.x + ad.x + s0;
    float l1 = as.y + ad.y + s1;
    float l2 = as.z + ad.z + s2;
    float l3 = as.w + ad.w + s3;
    l0 = l0 >= 0.f ? l0 : NEG_SLOPE * l0;
    l1 = l1 >= 0.f ? l1 : NEG_SLOPE * l1;
    l2 = l2 >= 0.f ? l2 : NEG_SLOPE * l2;
    l3 = l3 >= 0.f ? l3 : NEG_SLOPE * l3;
    float4 ev = make_float4(__expf(l0), __expf(l1), __expf(l2), __expf(l3));
    int pos = atomicAdd(&g_cursor[dst], 1);
    g_src_perm[pos] = src;
    *(float4*)(g_ev_perm + (size_t)pos * HEADS) = ev;
}

// ---------------- aggregate: warp per node, no atomics, fused epilogue -----
__global__ __launch_bounds__(256) void k_agg(float* __restrict__ out,
                                             const float* __restrict__ gat_bias,
                                             const float* __restrict__ bias) {
    int n = blockIdx.x * 8 + (threadIdx.x >> 5);
    if (n >= N_NODES) return;
    int lane = threadIdx.x & 31;
    int beg = g_rowptr[n];
    int end = g_rowptr[n + 1];
    float a0 = 0.f, a1 = 0.f, a2 = 0.f, a3 = 0.f;
    float d0 = 0.f, d1 = 0.f, d2 = 0.f, d3 = 0.f;
    #pragma unroll 2
    for (int idx = beg; idx < end; idx++) {
        int src = g_src_perm[idx];
        float4 ev = *(const float4*)(g_ev_perm + (size_t)idx * HEADS);
        const float* xr = g_xh + (size_t)src * HC;
        a0 += ev.x * xr[lane];
        a1 += ev.y * xr[32 + lane];
        a2 += ev.z * xr[64 + lane];
        a3 += ev.w * xr[96 + lane];
        d0 += ev.x; d1 += ev.y; d2 += ev.z; d3 += ev.w;
    }
    float m = 0.f;
    if (d0 > 0.f) m += a0 / d0;
    if (d1 > 0.f) m += a1 / d1;
    if (d2 > 0.f) m += a2 / d2;
    if (d3 > 0.f) m += a3 / d3;
    float gb = 0.25f * (gat_bias[lane] + gat_bias[32 + lane] +
                        gat_bias[64 + lane] + gat_bias[96 + lane]);
    float v = 0.25f * m + gb + bias[lane];
    out[(size_t)n * CH + lane] = v > 0.f ? v : 0.f;
}

extern "C" void kernel_launch(void* const* d_in, const int* in_sizes, int n_in,
                              void* d_out, int out_size) {
    const float* x        = (const float*)d_in[0];
    const int*   ei       = (const int*)  d_in[1];
    const float* ea       = (const float*)d_in[2];
    const float* W        = (const float*)d_in[3];
    const float* att_src  = (const float*)d_in[4];
    const float* att_dst  = (const float*)d_in[5];
    const float* W_edge   = (const float*)d_in[6];
    const float* att_edge = (const float*)d_in[7];
    const float* gat_bias = (const float*)d_in[8];
    const float* bias     = (const float*)d_in[9];
    float* out = (float*)d_out;

    k_init        <<<(N_NODES + 255) / 256, 256>>>();
    k_weff        <<<1, 128>>>(W_edge, att_edge);
    k_wpack       <<<32, 256>>>(W);
    k_count       <<<(N_EDGES + 255) / 256, 256>>>(ei);
    k_gemm        <<<(N_NODES + 127) / 128, 256>>>(x, att_src, att_dst);
    k_scan1       <<<N_SCAN_BLKS, 256>>>();
    k_scan2       <<<1, 32>>>();
    k_scan3       <<<(N_NODES + 255) / 256, 256>>>();
    k_edge_scatter<<<N_EDGES / 256, 256>>>(ei, ea);
    k_agg         <<<(N_NODES + 7) / 8, 256>>>(out, gat_bias, bias);
}

// round 5
// speedup vs baseline: 2.5614x; 1.0010x over previous
#include <cuda_runtime.h>
#include <cuda_fp16.h>

#define N_NODES 100000
#define N_EDGES 1600000
#define IN_CH 128
#define ED_CH 32
#define HEADS 4
#define CH 32
#define HC 128
#define NEG_SLOPE 0.2f
#define SCAN_BLK 1024
#define N_SCAN_BLKS ((N_NODES + SCAN_BLK - 1) / SCAN_BLK)   // 98

// prep kernel block ranges
#define PREP_COUNT_BLKS 1563            // 4 edges/thread, 256 thr
#define PREP_WPACK_BLKS 32
#define PREP_TOTAL_BLKS (PREP_COUNT_BLKS + PREP_WPACK_BLKS + 1)

// ---------------- scratch (no runtime allocation allowed) ----------------
__device__ __half g_xh_h[N_NODES * HC];         // 25.6 MB fp16 xh, [N,H,C]
__device__ float g_asrc[N_NODES * HEADS];
__device__ float g_adst[N_NODES * HEADS];
__device__ float g_weff[ED_CH * HEADS];         // folded W_edge @ att_edge
__device__ uint2 g_Wp[16 * 16 * 32];            // W packed as tf32 B-fragments
__device__ float g_ev_perm[N_EDGES * HEADS];    // expv permuted by dst
__device__ int   g_src_perm[N_EDGES];           // src permuted by dst
__device__ int   g_count[N_NODES];
__device__ int   g_rowptr[N_NODES + 1];
__device__ int   g_cursor[N_NODES];
__device__ int   g_bsum[N_SCAN_BLKS];
__device__ int   g_boff[N_SCAN_BLKS];

__device__ __forceinline__ unsigned tf32r(float f) {
    unsigned r;
    asm("cvt.rna.tf32.f32 %0, %1;" : "=r"(r) : "f"(f));
    return r;
}

__device__ __forceinline__ void mma_tf32(float c[4], unsigned a0, unsigned a1,
                                         unsigned a2, unsigned a3,
                                         unsigned b0, unsigned b1) {
    asm volatile(
        "mma.sync.aligned.m16n8k8.row.col.f32.tf32.tf32.f32 "
        "{%0,%1,%2,%3},{%4,%5,%6,%7},{%8,%9},{%0,%1,%2,%3};"
        : "+f"(c[0]), "+f"(c[1]), "+f"(c[2]), "+f"(c[3])
        : "r"(a0), "r"(a1), "r"(a2), "r"(a3), "r"(b0), "r"(b1));
}

// ---------------- init: zero edge counts ------------------------------------
__global__ void k_init() {
    int i = blockIdx.x * blockDim.x + threadIdx.x;
    if (i < N_NODES) g_count[i] = 0;
}

// ---------------- fused prep: degree count | W pack | w_eff -----------------
__global__ __launch_bounds__(256) void k_prep(const int* __restrict__ ei,
                                              const float* __restrict__ W,
                                              const float* __restrict__ W_edge,
                                              const float* __restrict__ att_edge) {
    int b = blockIdx.x;
    int tid = threadIdx.x;
    if (b < PREP_COUNT_BLKS) {
        // degree count, 4 edges per thread via int4
        int i = b * 256 + tid;                      // int4 index
        if (i * 4 < N_EDGES) {
            int4 d4 = *(const int4*)(ei + N_EDGES + i * 4);
            atomicAdd(&g_count[d4.x], 1);
            atomicAdd(&g_count[d4.y], 1);
            atomicAdd(&g_count[d4.z], 1);
            atomicAdd(&g_count[d4.w], 1);
        }
    } else if (b < PREP_COUNT_BLKS + PREP_WPACK_BLKS) {
        // pack W into tf32 B-fragment order
        int t = (b - PREP_COUNT_BLKS) * 256 + tid;  // 0..8191
        int lane = t & 31;
        int n = (t >> 5) & 15;
        int kk = t >> 9;
        int krow = 8 * kk + (lane & 3);
        int col = 8 * n + (lane >> 2);
        uint2 bb;
        bb.x = tf32r(W[krow * HC + col]);
        bb.y = tf32r(W[(krow + 4) * HC + col]);
        g_Wp[t] = bb;
        (void)n;
    } else {
        // w_eff[d,h] = sum_c W_edge[d, h*C+c] * att_edge[h,c]
        if (tid < 128) {
            int d = tid >> 2, h = tid & 3;
            float s = 0.f;
            #pragma unroll
            for (int c = 0; c < CH; c++)
                s += W_edge[d * HC + h * CH + c] * att_edge[h * CH + c];
            g_weff[d * HEADS + h] = s;
        }
    }
}

// ---------------- xh = x @ W via tf32 mma + fused a_src/a_dst ---------------
// 256 threads = 8 warps; warp computes 16 rows x 128 cols. No smem, no syncs.
__global__ __launch_bounds__(256) void k_gemm(const float* __restrict__ x,
                                              const float* __restrict__ att_src,
                                              const float* __restrict__ att_dst) {
    int tid  = threadIdx.x;
    int warp = tid >> 5;
    int lane = tid & 31;
    int grp  = lane >> 2;      // 0..7 (row within fragment)
    int q    = lane & 3;       // quad id (col group)

    int r0  = blockIdx.x * 128 + warp * 16;
    int rlo = r0 + grp;
    int rhi = rlo + 8;
    int rloL = rlo < N_NODES ? rlo : N_NODES - 1;
    int rhiL = rhi < N_NODES ? rhi : N_NODES - 1;
    const float* xlo = x + (size_t)rloL * IN_CH;
    const float* xhi = x + (size_t)rhiL * IN_CH;

    float c[16][4];
    #pragma unroll
    for (int n = 0; n < 16; n++) { c[n][0] = c[n][1] = c[n][2] = c[n][3] = 0.f; }

    #pragma unroll
    for (int kk = 0; kk < 16; kk++) {
        int k0 = 8 * kk;
        unsigned a0 = tf32r(__ldg(xlo + k0 + q));
        unsigned a1 = tf32r(__ldg(xhi + k0 + q));
        unsigned a2 = tf32r(__ldg(xlo + k0 + q + 4));
        unsigned a3 = tf32r(__ldg(xhi + k0 + q + 4));
        const uint2* wp = g_Wp + (size_t)kk * 16 * 32 + lane;
        #pragma unroll
        for (int n = 0; n < 16; n++) {
            uint2 b = __ldg(wp + n * 32);
            mma_tf32(c[n], a0, a1, a2, a3, b.x, b.y);
        }
    }

    // epilogue: store xh (fp16) + accumulate per-head attention dots
    float sl[4] = {0.f, 0.f, 0.f, 0.f}, dl[4] = {0.f, 0.f, 0.f, 0.f};
    float sh[4] = {0.f, 0.f, 0.f, 0.f}, dh[4] = {0.f, 0.f, 0.f, 0.f};
    bool wlo = rlo < N_NODES, whi = rhi < N_NODES;
    #pragma unroll
    for (int n = 0; n < 16; n++) {
        int col = 8 * n + 2 * q;
        int h = n >> 2;
        float as0 = __ldg(att_src + col), as1 = __ldg(att_src + col + 1);
        float ad0 = __ldg(att_dst + col), ad1 = __ldg(att_dst + col + 1);
        if (wlo)
            *(__half2*)(g_xh_h + (size_t)rlo * HC + col) =
                __floats2half2_rn(c[n][0], c[n][1]);
        if (whi)
            *(__half2*)(g_xh_h + (size_t)rhi * HC + col) =
                __floats2half2_rn(c[n][2], c[n][3]);
        sl[h] += c[n][0] * as0 + c[n][1] * as1;
        dl[h] += c[n][0] * ad0 + c[n][1] * ad1;
        sh[h] += c[n][2] * as0 + c[n][3] * as1;
        dh[h] += c[n][2] * ad0 + c[n][3] * ad1;
    }
    #pragma unroll
    for (int h = 0; h < 4; h++) {
        #pragma unroll
        for (int o = 1; o < 4; o <<= 1) {
            sl[h] += __shfl_xor_sync(0xffffffffu, sl[h], o);
            dl[h] += __shfl_xor_sync(0xffffffffu, dl[h], o);
            sh[h] += __shfl_xor_sync(0xffffffffu, sh[h], o);
            dh[h] += __shfl_xor_sync(0xffffffffu, dh[h], o);
        }
    }
    if (q == 0) {
        #pragma unroll
        for (int h = 0; h < 4; h++) {
            if (wlo) { g_asrc[rlo * HEADS + h] = sl[h]; g_adst[rlo * HEADS + h] = dl[h]; }
            if (whi) { g_asrc[rhi * HEADS + h] = sh[h]; g_adst[rhi * HEADS + h] = dh[h]; }
        }
    }
}

// ---------------- scan step 1: per-1024-block exclusive scan ---------------
__global__ __launch_bounds__(256) void k_scan1() {
    int b = blockIdx.x;
    int base = b * SCAN_BLK;
    int tid = threadIdx.x;
    int lane = tid & 31, w = tid >> 5;
    int v[4], ts = 0;
    #pragma unroll
    for (int j = 0; j < 4; j++) {
        int idx = base + tid * 4 + j;
        v[j] = (idx < N_NODES) ? g_count[idx] : 0;
        ts += v[j];
    }
    int incl = ts;
    #pragma unroll
    for (int o = 1; o < 32; o <<= 1) {
        int t = __shfl_up_sync(0xffffffffu, incl, o);
        if (lane >= o) incl += t;
    }
    __shared__ int wsum[8];
    if (lane == 31) wsum[w] = incl;
    __syncthreads();
    if (w == 0 && lane < 8) {
        int t = wsum[lane];
        #pragma unroll
        for (int o = 1; o < 8; o <<= 1) {
            int u = __shfl_up_sync(0xffu, t, o);
            if (lane >= o) t += u;
        }
        wsum[lane] = t;
    }
    __syncthreads();
    int excl = incl - ts + (w > 0 ? wsum[w - 1] : 0);
    int run = excl;
    #pragma unroll
    for (int j = 0; j < 4; j++) {
        int idx = base + tid * 4 + j;
        if (idx < N_NODES) g_rowptr[idx] = run;
        run += v[j];
    }
    __syncthreads();
    if (tid == 255) g_bsum[b] = wsum[7];
}

// ---------------- scan step 2: scan the 98 block sums ----------------------
__global__ void k_scan2() {
    if (threadIdx.x == 0) {
        int run = 0;
        for (int b = 0; b < N_SCAN_BLKS; b++) { g_boff[b] = run; run += g_bsum[b]; }
        g_rowptr[N_NODES] = N_EDGES;
    }
}

// ---------------- scan step 3: add offsets, init cursors -------------------
__global__ void k_scan3() {
    int i = blockIdx.x * blockDim.x + threadIdx.x;
    if (i >= N_NODES) return;
    int r = g_rowptr[i] + g_boff[i >> 10];
    g_rowptr[i] = r;
    g_cursor[i] = r;
}

// ---------------- fused edge pass: logits->exp + CSR scatter ---------------
__global__ __launch_bounds__(256) void k_edge_scatter(const int* __restrict__ ei,
                                                      const float* __restrict__ ea) {
    __shared__ float sEA[256][33];
    __shared__ float4 sW[32];
    int tid = threadIdx.x;
    int e0  = blockIdx.x * 256;

    if (tid < 32) sW[tid] = *(const float4*)(g_weff + tid * 4);

    const float4* gsrc = (const float4*)(ea + (size_t)e0 * ED_CH);
    #pragma unroll
    for (int k = 0; k < 8; k++) {
        int idx = tid + k * 256;
        float4 v = gsrc[idx];
        int row = idx >> 3;
        int col = (idx & 7) * 4;
        sEA[row][col + 0] = v.x; sEA[row][col + 1] = v.y;
        sEA[row][col + 2] = v.z; sEA[row][col + 3] = v.w;
    }
    __syncthreads();

    int e = e0 + tid;
    float s0 = 0.f, s1 = 0.f, s2 = 0.f, s3 = 0.f;
    #pragma unroll
    for (int d = 0; d < 32; d++) {
        float v = sEA[tid][d];
        float4 w = sW[d];
        s0 += v * w.x; s1 += v * w.y; s2 += v * w.z; s3 += v * w.w;
    }
    int src = ei[e];
    int dst = ei[N_EDGES + e];
    float4 as = *(const float4*)(g_asrc + src * HEADS);
    float4 ad = *(const float4*)(g_adst + dst * HEADS);
    float l0 = as.x + ad.x + s0;
    float l1 = as.y + ad.y + s1;
    float l2 = as.z + ad.z + s2;
    float l3 = as.w + ad.w + s3;
    l0 = l0 >= 0.f ? l0 : NEG_SLOPE * l0;
    l1 = l1 >= 0.f ? l1 : NEG_SLOPE * l1;
    l2 = l2 >= 0.f ? l2 : NEG_SLOPE * l2;
    l3 = l3 >= 0.f ? l3 : NEG_SLOPE * l3;
    float4 ev = make_float4(__expf(l0), __expf(l1), __expf(l2), __expf(l3));
    int pos = atomicAdd(&g_cursor[dst], 1);
    g_src_perm[pos] = src;
    *(float4*)(g_ev_perm + (size_t)pos * HEADS) = ev;
}

// ---------------- aggregate: warp per node, fp16 gathers, fused epilogue ---
__global__ __launch_bounds__(256) void k_agg(float* __restrict__ out,
                                             const float* __restrict__ gat_bias,
                                             const float* __restrict__ bias) {
    int n = blockIdx.x * 8 + (threadIdx.x >> 5);
    if (n >= N_NODES) return;
    int lane = threadIdx.x & 31;
    int beg = g_rowptr[n];
    int end = g_rowptr[n + 1];
    float a0 = 0.f, a1 = 0.f, a2 = 0.f, a3 = 0.f;
    float d0 = 0.f, d1 = 0.f, d2 = 0.f, d3 = 0.f;
    #pragma unroll 4
    for (int idx = beg; idx < end; idx++) {
        int src = g_src_perm[idx];
        float4 ev = *(const float4*)(g_ev_perm + (size_t)idx * HEADS);
        const __half* xr = g_xh_h + (size_t)src * HC;
        a0 += ev.x * __half2float(__ldg(xr + lane));
        a1 += ev.y * __half2float(__ldg(xr + 32 + lane));
        a2 += ev.z * __half2float(__ldg(xr + 64 + lane));
        a3 += ev.w * __half2float(__ldg(xr + 96 + lane));
        d0 += ev.x; d1 += ev.y; d2 += ev.z; d3 += ev.w;
    }
    float m = 0.f;
    if (d0 > 0.f) m += a0 / d0;
    if (d1 > 0.f) m += a1 / d1;
    if (d2 > 0.f) m += a2 / d2;
    if (d3 > 0.f) m += a3 / d3;
    float gb = 0.25f * (gat_bias[lane] + gat_bias[32 + lane] +
                        gat_bias[64 + lane] + gat_bias[96 + lane]);
    float v = 0.25f * m + gb + bias[lane];
    out[(size_t)n * CH + lane] = v > 0.f ? v : 0.f;
}

extern "C" void kernel_launch(void* const* d_in, const int* in_sizes, int n_in,
                              void* d_out, int out_size) {
    const float* x        = (const float*)d_in[0];
    const int*   ei       = (const int*)  d_in[1];
    const float* ea       = (const float*)d_in[2];
    const float* W        = (const float*)d_in[3];
    const float* att_src  = (const float*)d_in[4];
    const float* att_dst  = (const float*)d_in[5];
    const float* W_edge   = (const float*)d_in[6];
    const float* att_edge = (const float*)d_in[7];
    const float* gat_bias = (const float*)d_in[8];
    const float* bias     = (const float*)d_in[9];
    float* out = (float*)d_out;

    k_init        <<<(N_NODES + 255) / 256, 256>>>();
    k_prep        <<<PREP_TOTAL_BLKS, 256>>>(ei, W, W_edge, att_edge);
    k_gemm        <<<(N_NODES + 127) / 128, 256>>>(x, att_src, att_dst);
    k_scan1       <<<N_SCAN_BLKS, 256>>>();
    k_scan2       <<<1, 32>>>();
    k_scan3       <<<(N_NODES + 255) / 256, 256>>>();
    k_edge_scatter<<<N_EDGES / 256, 256>>>(ei, ea);
    k_agg         <<<(N_NODES + 7) / 8, 256>>>(out, gat_bias, bias);
}

// round 6
// speedup vs baseline: 3.4616x; 1.3515x over previous
#include <cuda_runtime.h>
#include <cuda_fp16.h>

#define N_NODES 100000
#define N_EDGES 1600000
#define IN_CH 128
#define ED_CH 32
#define HEADS 4
#define CH 32
#define HC 128
#define NEG_SLOPE 0.2f
#define SCAN_BLK 1024
#define N_SCAN_BLKS ((N_NODES + SCAN_BLK - 1) / SCAN_BLK)   // 98

// prep kernel block ranges
#define PREP_COUNT_BLKS 1563            // 4 edges/thread, 256 thr
#define PREP_WPACK_BLKS 32
#define PREP_TOTAL_BLKS (PREP_COUNT_BLKS + PREP_WPACK_BLKS + 1)

// ---------------- scratch (no runtime allocation allowed) ----------------
__device__ __half g_xh_h[N_NODES * HC];         // 25.6 MB fp16 xh, [N,H,C]
__device__ float g_asrc[N_NODES * HEADS];
__device__ float g_adst[N_NODES * HEADS];
__device__ float g_weff[ED_CH * HEADS];         // folded W_edge @ att_edge
__device__ uint2 g_Wp[16 * 16 * 32];            // W packed as tf32 B-fragments
__device__ __half g_evh_perm[N_EDGES * HEADS];  // 12.8 MB expv (fp16) by dst
__device__ int   g_src_perm[N_EDGES];           // src permuted by dst
__device__ int   g_count[N_NODES];
__device__ int   g_rowptr[N_NODES + 1];
__device__ int   g_cursor[N_NODES];
__device__ int   g_bsum[N_SCAN_BLKS];
__device__ int   g_boff[N_SCAN_BLKS];

__device__ __forceinline__ unsigned tf32r(float f) {
    unsigned r;
    asm("cvt.rna.tf32.f32 %0, %1;" : "=r"(r) : "f"(f));
    return r;
}

__device__ __forceinline__ void mma_tf32(float c[4], unsigned a0, unsigned a1,
                                         unsigned a2, unsigned a3,
                                         unsigned b0, unsigned b1) {
    asm volatile(
        "mma.sync.aligned.m16n8k8.row.col.f32.tf32.tf32.f32 "
        "{%0,%1,%2,%3},{%4,%5,%6,%7},{%8,%9},{%0,%1,%2,%3};"
        : "+f"(c[0]), "+f"(c[1]), "+f"(c[2]), "+f"(c[3])
        : "r"(a0), "r"(a1), "r"(a2), "r"(a3), "r"(b0), "r"(b1));
}

// ---------------- init: zero edge counts ------------------------------------
__global__ void k_init() {
    int i = blockIdx.x * blockDim.x + threadIdx.x;
    if (i < N_NODES) g_count[i] = 0;
}

// ---------------- fused prep: degree count | W pack | w_eff -----------------
__global__ __launch_bounds__(256) void k_prep(const int* __restrict__ ei,
                                              const float* __restrict__ W,
                                              const float* __restrict__ W_edge,
                                              const float* __restrict__ att_edge) {
    int b = blockIdx.x;
    int tid = threadIdx.x;
    if (b < PREP_COUNT_BLKS) {
        int i = b * 256 + tid;                      // int4 index
        if (i * 4 < N_EDGES) {
            int4 d4 = *(const int4*)(ei + N_EDGES + i * 4);
            atomicAdd(&g_count[d4.x], 1);
            atomicAdd(&g_count[d4.y], 1);
            atomicAdd(&g_count[d4.z], 1);
            atomicAdd(&g_count[d4.w], 1);
        }
    } else if (b < PREP_COUNT_BLKS + PREP_WPACK_BLKS) {
        int t = (b - PREP_COUNT_BLKS) * 256 + tid;  // 0..8191
        int lane = t & 31;
        int n = (t >> 5) & 15;
        int kk = t >> 9;
        int krow = 8 * kk + (lane & 3);
        int col = 8 * n + (lane >> 2);
        uint2 bb;
        bb.x = tf32r(W[krow * HC + col]);
        bb.y = tf32r(W[(krow + 4) * HC + col]);
        g_Wp[t] = bb;
    } else {
        if (tid < 128) {
            int d = tid >> 2, h = tid & 3;
            float s = 0.f;
            #pragma unroll
            for (int c = 0; c < CH; c++)
                s += W_edge[d * HC + h * CH + c] * att_edge[h * CH + c];
            g_weff[d * HEADS + h] = s;
        }
    }
}

// ---------------- xh = x @ W via tf32 mma + fused a_src/a_dst ---------------
__global__ __launch_bounds__(256) void k_gemm(const float* __restrict__ x,
                                              const float* __restrict__ att_src,
                                              const float* __restrict__ att_dst) {
    int tid  = threadIdx.x;
    int warp = tid >> 5;
    int lane = tid & 31;
    int grp  = lane >> 2;      // 0..7 (row within fragment)
    int q    = lane & 3;       // quad id (col group)

    int r0  = blockIdx.x * 128 + warp * 16;
    int rlo = r0 + grp;
    int rhi = rlo + 8;
    int rloL = rlo < N_NODES ? rlo : N_NODES - 1;
    int rhiL = rhi < N_NODES ? rhi : N_NODES - 1;
    const float* xlo = x + (size_t)rloL * IN_CH;
    const float* xhi = x + (size_t)rhiL * IN_CH;

    float c[16][4];
    #pragma unroll
    for (int n = 0; n < 16; n++) { c[n][0] = c[n][1] = c[n][2] = c[n][3] = 0.f; }

    #pragma unroll
    for (int kk = 0; kk < 16; kk++) {
        int k0 = 8 * kk;
        unsigned a0 = tf32r(__ldg(xlo + k0 + q));
        unsigned a1 = tf32r(__ldg(xhi + k0 + q));
        unsigned a2 = tf32r(__ldg(xlo + k0 + q + 4));
        unsigned a3 = tf32r(__ldg(xhi + k0 + q + 4));
        const uint2* wp = g_Wp + (size_t)kk * 16 * 32 + lane;
        #pragma unroll
        for (int n = 0; n < 16; n++) {
            uint2 b = __ldg(wp + n * 32);
            mma_tf32(c[n], a0, a1, a2, a3, b.x, b.y);
        }
    }

    float sl[4] = {0.f, 0.f, 0.f, 0.f}, dl[4] = {0.f, 0.f, 0.f, 0.f};
    float sh[4] = {0.f, 0.f, 0.f, 0.f}, dh[4] = {0.f, 0.f, 0.f, 0.f};
    bool wlo = rlo < N_NODES, whi = rhi < N_NODES;
    #pragma unroll
    for (int n = 0; n < 16; n++) {
        int col = 8 * n + 2 * q;
        int h = n >> 2;
        float as0 = __ldg(att_src + col), as1 = __ldg(att_src + col + 1);
        float ad0 = __ldg(att_dst + col), ad1 = __ldg(att_dst + col + 1);
        if (wlo)
            *(__half2*)(g_xh_h + (size_t)rlo * HC + col) =
                __floats2half2_rn(c[n][0], c[n][1]);
        if (whi)
            *(__half2*)(g_xh_h + (size_t)rhi * HC + col) =
                __floats2half2_rn(c[n][2], c[n][3]);
        sl[h] += c[n][0] * as0 + c[n][1] * as1;
        dl[h] += c[n][0] * ad0 + c[n][1] * ad1;
        sh[h] += c[n][2] * as0 + c[n][3] * as1;
        dh[h] += c[n][2] * ad0 + c[n][3] * ad1;
    }
    #pragma unroll
    for (int h = 0; h < 4; h++) {
        #pragma unroll
        for (int o = 1; o < 4; o <<= 1) {
            sl[h] += __shfl_xor_sync(0xffffffffu, sl[h], o);
            dl[h] += __shfl_xor_sync(0xffffffffu, dl[h], o);
            sh[h] += __shfl_xor_sync(0xffffffffu, sh[h], o);
            dh[h] += __shfl_xor_sync(0xffffffffu, dh[h], o);
        }
    }
    if (q == 0) {
        #pragma unroll
        for (int h = 0; h < 4; h++) {
            if (wlo) { g_asrc[rlo * HEADS + h] = sl[h]; g_adst[rlo * HEADS + h] = dl[h]; }
            if (whi) { g_asrc[rhi * HEADS + h] = sh[h]; g_adst[rhi * HEADS + h] = dh[h]; }
        }
    }
}

// ---------------- scan step 1: per-1024-block exclusive scan ---------------
__global__ __launch_bounds__(256) void k_scan1() {
    int b = blockIdx.x;
    int base = b * SCAN_BLK;
    int tid = threadIdx.x;
    int lane = tid & 31, w = tid >> 5;
    int v[4], ts = 0;
    #pragma unroll
    for (int j = 0; j < 4; j++) {
        int idx = base + tid * 4 + j;
        v[j] = (idx < N_NODES) ? g_count[idx] : 0;
        ts += v[j];
    }
    int incl = ts;
    #pragma unroll
    for (int o = 1; o < 32; o <<= 1) {
        int t = __shfl_up_sync(0xffffffffu, incl, o);
        if (lane >= o) incl += t;
    }
    __shared__ int wsum[8];
    if (lane == 31) wsum[w] = incl;
    __syncthreads();
    if (w == 0 && lane < 8) {
        int t = wsum[lane];
        #pragma unroll
        for (int o = 1; o < 8; o <<= 1) {
            int u = __shfl_up_sync(0xffu, t, o);
            if (lane >= o) t += u;
        }
        wsum[lane] = t;
    }
    __syncthreads();
    int excl = incl - ts + (w > 0 ? wsum[w - 1] : 0);
    int run = excl;
    #pragma unroll
    for (int j = 0; j < 4; j++) {
        int idx = base + tid * 4 + j;
        if (idx < N_NODES) g_rowptr[idx] = run;
        run += v[j];
    }
    __syncthreads();
    if (tid == 255) g_bsum[b] = wsum[7];
}

// ---------------- scan step 2: scan the 98 block sums ----------------------
__global__ void k_scan2() {
    if (threadIdx.x == 0) {
        int run = 0;
        for (int b = 0; b < N_SCAN_BLKS; b++) { g_boff[b] = run; run += g_bsum[b]; }
        g_rowptr[N_NODES] = N_EDGES;
    }
}

// ---------------- scan step 3: add offsets, init cursors -------------------
__global__ void k_scan3() {
    int i = blockIdx.x * blockDim.x + threadIdx.x;
    if (i >= N_NODES) return;
    int r = g_rowptr[i] + g_boff[i >> 10];
    g_rowptr[i] = r;
    g_cursor[i] = r;
}

// ---------------- fused edge pass: logits->exp + CSR scatter ---------------
__global__ __launch_bounds__(256) void k_edge_scatter(const int* __restrict__ ei,
                                                      const float* __restrict__ ea) {
    __shared__ float sEA[256][33];
    __shared__ float4 sW[32];
    int tid = threadIdx.x;
    int e0  = blockIdx.x * 256;

    if (tid < 32) sW[tid] = *(const float4*)(g_weff + tid * 4);

    const float4* gsrc = (const float4*)(ea + (size_t)e0 * ED_CH);
    #pragma unroll
    for (int k = 0; k < 8; k++) {
        int idx = tid + k * 256;
        float4 v = gsrc[idx];
        int row = idx >> 3;
        int col = (idx & 7) * 4;
        sEA[row][col + 0] = v.x; sEA[row][col + 1] = v.y;
        sEA[row][col + 2] = v.z; sEA[row][col + 3] = v.w;
    }
    __syncthreads();

    int e = e0 + tid;
    float s0 = 0.f, s1 = 0.f, s2 = 0.f, s3 = 0.f;
    #pragma unroll
    for (int d = 0; d < 32; d++) {
        float v = sEA[tid][d];
        float4 w = sW[d];
        s0 += v * w.x; s1 += v * w.y; s2 += v * w.z; s3 += v * w.w;
    }
    int src = ei[e];
    int dst = ei[N_EDGES + e];
    float4 as = *(const float4*)(g_asrc + src * HEADS);
    float4 ad = *(const float4*)(g_adst + dst * HEADS);
    float l0 = as.x + ad.x + s0;
    float l1 = as.y + ad.y + s1;
    float l2 = as.z + ad.z + s2;
    float l3 = as.w + ad.w + s3;
    l0 = l0 >= 0.f ? l0 : NEG_SLOPE * l0;
    l1 = l1 >= 0.f ? l1 : NEG_SLOPE * l1;
    l2 = l2 >= 0.f ? l2 : NEG_SLOPE * l2;
    l3 = l3 >= 0.f ? l3 : NEG_SLOPE * l3;
    __half2 p0 = __floats2half2_rn(__expf(l0), __expf(l1));
    __half2 p1 = __floats2half2_rn(__expf(l2), __expf(l3));
    uint2 packed;
    packed.x = *(unsigned*)&p0;
    packed.y = *(unsigned*)&p1;
    int pos = atomicAdd(&g_cursor[dst], 1);
    g_src_perm[pos] = src;
    *(uint2*)(g_evh_perm + (size_t)pos * HEADS) = packed;
}

// ---------------- aggregate: lane-per-(head,4ch), 1 LDG.64 per edge --------
__global__ __launch_bounds__(256) void k_agg(float* __restrict__ out,
                                             const float* __restrict__ gat_bias,
                                             const float* __restrict__ bias) {
    int n = blockIdx.x * 8 + (threadIdx.x >> 5);
    if (n >= N_NODES) return;
    int lane = threadIdx.x & 31;
    int h  = lane >> 3;            // head owned by this lane
    int c0 = 4 * (lane & 7);       // channel base (0..28)
    int beg = g_rowptr[n];
    int end = g_rowptr[n + 1];
    float a0 = 0.f, a1 = 0.f, a2 = 0.f, a3 = 0.f, dsum = 0.f;
    #pragma unroll 4
    for (int idx = beg; idx < end; idx++) {
        int src = __ldg(g_src_perm + idx);
        float ev = __half2float(__ldg(g_evh_perm + (size_t)idx * HEADS + h));
        uint2 xw = __ldg((const uint2*)(g_xh_h + (size_t)src * HC) + lane);
        float2 f0 = __half22float2(*(__half2*)&xw.x);
        float2 f1 = __half22float2(*(__half2*)&xw.y);
        a0 += ev * f0.x; a1 += ev * f0.y;
        a2 += ev * f1.x; a3 += ev * f1.y;
        dsum += ev;
    }
    float inv = dsum > 0.f ? 1.f / dsum : 0.f;
    a0 *= inv; a1 *= inv; a2 *= inv; a3 *= inv;
    // reduce across the 4 heads (lanes l, l^8, l^16, l^24)
    #pragma unroll
    for (int o = 8; o < 32; o <<= 1) {
        a0 += __shfl_xor_sync(0xffffffffu, a0, o);
        a1 += __shfl_xor_sync(0xffffffffu, a1, o);
        a2 += __shfl_xor_sync(0xffffffffu, a2, o);
        a3 += __shfl_xor_sync(0xffffffffu, a3, o);
    }
    if (lane < 8) {
        float r[4] = {a0, a1, a2, a3};
        float4 v4;
        float* vp = (float*)&v4;
        #pragma unroll
        for (int j = 0; j < 4; j++) {
            int c = c0 + j;
            float gb = 0.25f * (__ldg(gat_bias + c)      + __ldg(gat_bias + 32 + c) +
                                __ldg(gat_bias + 64 + c) + __ldg(gat_bias + 96 + c));
            float v = 0.25f * r[j] + gb + __ldg(bias + c);
            vp[j] = v > 0.f ? v : 0.f;
        }
        *(float4*)(out + (size_t)n * CH + c0) = v4;
    }
}

extern "C" void kernel_launch(void* const* d_in, const int* in_sizes, int n_in,
                              void* d_out, int out_size) {
    const float* x        = (const float*)d_in[0];
    const int*   ei       = (const int*)  d_in[1];
    const float* ea       = (const float*)d_in[2];
    const float* W        = (const float*)d_in[3];
    const float* att_src  = (const float*)d_in[4];
    const float* att_dst  = (const float*)d_in[5];
    const float* W_edge   = (const float*)d_in[6];
    const float* att_edge = (const float*)d_in[7];
    const float* gat_bias = (const float*)d_in[8];
    const float* bias     = (const float*)d_in[9];
    float* out = (float*)d_out;

    k_init        <<<(N_NODES + 255) / 256, 256>>>();
    k_prep        <<<PREP_TOTAL_BLKS, 256>>>(ei, W, W_edge, att_edge);
    k_gemm        <<<(N_NODES + 127) / 128, 256>>>(x, att_src, att_dst);
    k_scan1       <<<N_SCAN_BLKS, 256>>>();
    k_scan2       <<<1, 32>>>();
    k_scan3       <<<(N_NODES + 255) / 256, 256>>>();
    k_edge_scatter<<<N_EDGES / 256, 256>>>(ei, ea);
    k_agg         <<<(N_NODES + 7) / 8, 256>>>(out, gat_bias, bias);
}

// round 7
// speedup vs baseline: 3.5338x; 1.0209x over previous
#include <cuda_runtime.h>
#include <cuda_fp16.h>

#define N_NODES 100000
#define N_EDGES 1600000
#define IN_CH 128
#define ED_CH 32
#define HEADS 4
#define CH 32
#define HC 128
#define NEG_SLOPE 0.2f
#define SCAN_BLK 1024
#define N_SCAN_BLKS ((N_NODES + SCAN_BLK - 1) / SCAN_BLK)   // 98

// ---------------- scratch (no runtime allocation allowed) ----------------
__device__ __half g_xh_h[N_NODES * HC];         // 25.6 MB fp16 xh, [N,H,C]
__device__ float g_asrc[N_NODES * HEADS];
__device__ float g_adst[N_NODES * HEADS];
__device__ float g_weff[ED_CH * HEADS];         // folded W_edge @ att_edge
__device__ uint2 g_Wp[16 * 16 * 32];            // W packed as tf32 B-fragments
__device__ uint4 g_rec[N_EDGES];                // {src, ev01(h2), ev23(h2), 0} by dst
__device__ int   g_count[N_NODES];
__device__ int   g_rowptr[N_NODES + 1];
__device__ int   g_cursor[N_NODES];
__device__ int   g_bsum[N_SCAN_BLKS];
__device__ int   g_boff[N_SCAN_BLKS];

__device__ __forceinline__ unsigned tf32r(float f) {
    unsigned r;
    asm("cvt.rna.tf32.f32 %0, %1;" : "=r"(r) : "f"(f));
    return r;
}

__device__ __forceinline__ void mma_tf32(float c[4], unsigned a0, unsigned a1,
                                         unsigned a2, unsigned a3,
                                         unsigned b0, unsigned b1) {
    asm volatile(
        "mma.sync.aligned.m16n8k8.row.col.f32.tf32.tf32.f32 "
        "{%0,%1,%2,%3},{%4,%5,%6,%7},{%8,%9},{%0,%1,%2,%3};"
        : "+f"(c[0]), "+f"(c[1]), "+f"(c[2]), "+f"(c[3])
        : "r"(a0), "r"(a1), "r"(a2), "r"(a3), "r"(b0), "r"(b1));
}

// ---------------- init: zero edge counts ------------------------------------
__global__ void k_init() {
    int i = blockIdx.x * blockDim.x + threadIdx.x;
    if (i < N_NODES) g_count[i] = 0;
}

// ---------------- degree count: 4 edges per thread via int4 -----------------
__global__ __launch_bounds__(256) void k_count(const int* __restrict__ ei) {
    int i = blockIdx.x * 256 + threadIdx.x;        // int4 index
    if (i * 4 < N_EDGES) {
        int4 d4 = *(const int4*)(ei + N_EDGES + i * 4);
        atomicAdd(&g_count[d4.x], 1);
        atomicAdd(&g_count[d4.y], 1);
        atomicAdd(&g_count[d4.z], 1);
        atomicAdd(&g_count[d4.w], 1);
    }
}

// ---------------- W pack (blocks 0..31) | w_eff (block 32) ------------------
__global__ __launch_bounds__(256) void k_wpw(const float* __restrict__ W,
                                             const float* __restrict__ W_edge,
                                             const float* __restrict__ att_edge) {
    int b = blockIdx.x;
    int tid = threadIdx.x;
    if (b < 32) {
        int t = b * 256 + tid;  // 0..8191
        int lane = t & 31;
        int n = (t >> 5) & 15;
        int kk = t >> 9;
        int krow = 8 * kk + (lane & 3);
        int col = 8 * n + (lane >> 2);
        uint2 bb;
        bb.x = tf32r(W[krow * HC + col]);
        bb.y = tf32r(W[(krow + 4) * HC + col]);
        g_Wp[t] = bb;
    } else if (tid < 128) {
        int d = tid >> 2, h = tid & 3;
        float s = 0.f;
        #pragma unroll
        for (int c = 0; c < CH; c++)
            s += W_edge[d * HC + h * CH + c] * att_edge[h * CH + c];
        g_weff[d * HEADS + h] = s;
    }
}

// ---------------- xh = x @ W via tf32 mma + fused a_src/a_dst ---------------
__global__ __launch_bounds__(256) void k_gemm(const float* __restrict__ x,
                                              const float* __restrict__ att_src,
                                              const float* __restrict__ att_dst) {
    int tid  = threadIdx.x;
    int warp = tid >> 5;
    int lane = tid & 31;
    int grp  = lane >> 2;      // 0..7 (row within fragment)
    int q    = lane & 3;       // quad id (col group)

    int r0  = blockIdx.x * 128 + warp * 16;
    int rlo = r0 + grp;
    int rhi = rlo + 8;
    int rloL = rlo < N_NODES ? rlo : N_NODES - 1;
    int rhiL = rhi < N_NODES ? rhi : N_NODES - 1;
    const float* xlo = x + (size_t)rloL * IN_CH;
    const float* xhi = x + (size_t)rhiL * IN_CH;

    float c[16][4];
    #pragma unroll
    for (int n = 0; n < 16; n++) { c[n][0] = c[n][1] = c[n][2] = c[n][3] = 0.f; }

    #pragma unroll
    for (int kk = 0; kk < 16; kk++) {
        int k0 = 8 * kk;
        unsigned a0 = tf32r(__ldg(xlo + k0 + q));
        unsigned a1 = tf32r(__ldg(xhi + k0 + q));
        unsigned a2 = tf32r(__ldg(xlo + k0 + q + 4));
        unsigned a3 = tf32r(__ldg(xhi + k0 + q + 4));
        const uint2* wp = g_Wp + (size_t)kk * 16 * 32 + lane;
        #pragma unroll
        for (int n = 0; n < 16; n++) {
            uint2 b = __ldg(wp + n * 32);
            mma_tf32(c[n], a0, a1, a2, a3, b.x, b.y);
        }
    }

    float sl[4] = {0.f, 0.f, 0.f, 0.f}, dl[4] = {0.f, 0.f, 0.f, 0.f};
    float sh[4] = {0.f, 0.f, 0.f, 0.f}, dh[4] = {0.f, 0.f, 0.f, 0.f};
    bool wlo = rlo < N_NODES, whi = rhi < N_NODES;
    #pragma unroll
    for (int n = 0; n < 16; n++) {
        int col = 8 * n + 2 * q;
        int h = n >> 2;
        float as0 = __ldg(att_src + col), as1 = __ldg(att_src + col + 1);
        float ad0 = __ldg(att_dst + col), ad1 = __ldg(att_dst + col + 1);
        if (wlo)
            *(__half2*)(g_xh_h + (size_t)rlo * HC + col) =
                __floats2half2_rn(c[n][0], c[n][1]);
        if (whi)
            *(__half2*)(g_xh_h + (size_t)rhi * HC + col) =
                __floats2half2_rn(c[n][2], c[n][3]);
        sl[h] += c[n][0] * as0 + c[n][1] * as1;
        dl[h] += c[n][0] * ad0 + c[n][1] * ad1;
        sh[h] += c[n][2] * as0 + c[n][3] * as1;
        dh[h] += c[n][2] * ad0 + c[n][3] * ad1;
    }
    #pragma unroll
    for (int h = 0; h < 4; h++) {
        #pragma unroll
        for (int o = 1; o < 4; o <<= 1) {
            sl[h] += __shfl_xor_sync(0xffffffffu, sl[h], o);
            dl[h] += __shfl_xor_sync(0xffffffffu, dl[h], o);
            sh[h] += __shfl_xor_sync(0xffffffffu, sh[h], o);
            dh[h] += __shfl_xor_sync(0xffffffffu, dh[h], o);
        }
    }
    if (q == 0) {
        #pragma unroll
        for (int h = 0; h < 4; h++) {
            if (wlo) { g_asrc[rlo * HEADS + h] = sl[h]; g_adst[rlo * HEADS + h] = dl[h]; }
            if (whi) { g_asrc[rhi * HEADS + h] = sh[h]; g_adst[rhi * HEADS + h] = dh[h]; }
        }
    }
}

// ---------------- scan step 1: per-1024-block exclusive scan ---------------
__global__ __launch_bounds__(256) void k_scan1() {
    int b = blockIdx.x;
    int base = b * SCAN_BLK;
    int tid = threadIdx.x;
    int lane = tid & 31, w = tid >> 5;
    int v[4], ts = 0;
    #pragma unroll
    for (int j = 0; j < 4; j++) {
        int idx = base + tid * 4 + j;
        v[j] = (idx < N_NODES) ? g_count[idx] : 0;
        ts += v[j];
    }
    int incl = ts;
    #pragma unroll
    for (int o = 1; o < 32; o <<= 1) {
        int t = __shfl_up_sync(0xffffffffu, incl, o);
        if (lane >= o) incl += t;
    }
    __shared__ int wsum[8];
    if (lane == 31) wsum[w] = incl;
    __syncthreads();
    if (w == 0 && lane < 8) {
        int t = wsum[lane];
        #pragma unroll
        for (int o = 1; o < 8; o <<= 1) {
            int u = __shfl_up_sync(0xffu, t, o);
            if (lane >= o) t += u;
        }
        wsum[lane] = t;
    }
    __syncthreads();
    int excl = incl - ts + (w > 0 ? wsum[w - 1] : 0);
    int run = excl;
    #pragma unroll
    for (int j = 0; j < 4; j++) {
        int idx = base + tid * 4 + j;
        if (idx < N_NODES) g_rowptr[idx] = run;
        run += v[j];
    }
    __syncthreads();
    if (tid == 255) g_bsum[b] = wsum[7];
}

// ---------------- scan step 2: scan the 98 block sums ----------------------
__global__ void k_scan2() {
    if (threadIdx.x == 0) {
        int run = 0;
        for (int b = 0; b < N_SCAN_BLKS; b++) { g_boff[b] = run; run += g_bsum[b]; }
        g_rowptr[N_NODES] = N_EDGES;
    }
}

// ---------------- scan step 3: add offsets, init cursors -------------------
__global__ void k_scan3() {
    int i = blockIdx.x * blockDim.x + threadIdx.x;
    if (i >= N_NODES) return;
    int r = g_rowptr[i] + g_boff[i >> 10];
    g_rowptr[i] = r;
    g_cursor[i] = r;
}

// ---------------- fused edge pass: logits->exp + CSR scatter ---------------
__global__ __launch_bounds__(256) void k_edge_scatter(const int* __restrict__ ei,
                                                      const float* __restrict__ ea) {
    __shared__ float sEA[256][33];
    __shared__ float4 sW[32];
    int tid = threadIdx.x;
    int e0  = blockIdx.x * 256;

    if (tid < 32) sW[tid] = *(const float4*)(g_weff + tid * 4);

    const float4* gsrc = (const float4*)(ea + (size_t)e0 * ED_CH);
    #pragma unroll
    for (int k = 0; k < 8; k++) {
        int idx = tid + k * 256;
        float4 v = gsrc[idx];
        int row = idx >> 3;
        int col = (idx & 7) * 4;
        sEA[row][col + 0] = v.x; sEA[row][col + 1] = v.y;
        sEA[row][col + 2] = v.z; sEA[row][col + 3] = v.w;
    }
    __syncthreads();

    int e = e0 + tid;
    float s0 = 0.f, s1 = 0.f, s2 = 0.f, s3 = 0.f;
    #pragma unroll
    for (int d = 0; d < 32; d++) {
        float v = sEA[tid][d];
        float4 w = sW[d];
        s0 += v * w.x; s1 += v * w.y; s2 += v * w.z; s3 += v * w.w;
    }
    int src = ei[e];
    int dst = ei[N_EDGES + e];
    float4 as = *(const float4*)(g_asrc + src * HEADS);
    float4 ad = *(const float4*)(g_adst + dst * HEADS);
    float l0 = as.x + ad.x + s0;
    float l1 = as.y + ad.y + s1;
    float l2 = as.z + ad.z + s2;
    float l3 = as.w + ad.w + s3;
    l0 = l0 >= 0.f ? l0 : NEG_SLOPE * l0;
    l1 = l1 >= 0.f ? l1 : NEG_SLOPE * l1;
    l2 = l2 >= 0.f ? l2 : NEG_SLOPE * l2;
    l3 = l3 >= 0.f ? l3 : NEG_SLOPE * l3;
    __half2 p0 = __floats2half2_rn(__expf(l0), __expf(l1));
    __half2 p1 = __floats2half2_rn(__expf(l2), __expf(l3));
    int pos = atomicAdd(&g_cursor[dst], 1);
    uint4 rec;
    rec.x = (unsigned)src;
    rec.y = *(unsigned*)&p0;
    rec.z = *(unsigned*)&p1;
    rec.w = 0u;
    g_rec[pos] = rec;          // single STG.128, one random sector
}

// ---------------- aggregate: lane-per-(head,4ch), 2 LDGs per edge ----------
__global__ __launch_bounds__(256) void k_agg(float* __restrict__ out,
                                             const float* __restrict__ gat_bias,
                                             const float* __restrict__ bias) {
    int n = blockIdx.x * 8 + (threadIdx.x >> 5);
    if (n >= N_NODES) return;
    int lane = threadIdx.x & 31;
    int h  = lane >> 3;            // head owned by this lane
    int c0 = 4 * (lane & 7);       // channel base (0..28)
    int beg = g_rowptr[n];
    int end = g_rowptr[n + 1];
    float a0 = 0.f, a1 = 0.f, a2 = 0.f, a3 = 0.f, dsum = 0.f;
    #pragma unroll 4
    for (int idx = beg; idx < end; idx++) {
        uint4 r = __ldg(g_rec + idx);                 // broadcast LDG.128
        int src = (int)r.x;
        unsigned evbits = (h & 2) ? r.z : r.y;
        float2 evp = __half22float2(*(__half2*)&evbits);
        float ev = (h & 1) ? evp.y : evp.x;
        uint2 xw = __ldg((const uint2*)(g_xh_h + (size_t)src * HC) + lane);
        float2 f0 = __half22float2(*(__half2*)&xw.x);
        float2 f1 = __half22float2(*(__half2*)&xw.y);
        a0 += ev * f0.x; a1 += ev * f0.y;
        a2 += ev * f1.x; a3 += ev * f1.y;
        dsum += ev;
    }
    float inv = dsum > 0.f ? 1.f / dsum : 0.f;
    a0 *= inv; a1 *= inv; a2 *= inv; a3 *= inv;
    #pragma unroll
    for (int o = 8; o < 32; o <<= 1) {
        a0 += __shfl_xor_sync(0xffffffffu, a0, o);
        a1 += __shfl_xor_sync(0xffffffffu, a1, o);
        a2 += __shfl_xor_sync(0xffffffffu, a2, o);
        a3 += __shfl_xor_sync(0xffffffffu, a3, o);
    }
    if (lane < 8) {
        float r[4] = {a0, a1, a2, a3};
        float4 v4;
        float* vp = (float*)&v4;
        #pragma unroll
        for (int j = 0; j < 4; j++) {
            int c = c0 + j;
            float gb = 0.25f * (__ldg(gat_bias + c)      + __ldg(gat_bias + 32 + c) +
                                __ldg(gat_bias + 64 + c) + __ldg(gat_bias + 96 + c));
            float v = 0.25f * r[j] + gb + __ldg(bias + c);
            vp[j] = v > 0.f ? v : 0.f;
        }
        *(float4*)(out + (size_t)n * CH + c0) = v4;
    }
}

extern "C" void kernel_launch(void* const* d_in, const int* in_sizes, int n_in,
                              void* d_out, int out_size) {
    const float* x        = (const float*)d_in[0];
    const int*   ei       = (const int*)  d_in[1];
    const float* ea       = (const float*)d_in[2];
    const float* W        = (const float*)d_in[3];
    const float* att_src  = (const float*)d_in[4];
    const float* att_dst  = (const float*)d_in[5];
    const float* W_edge   = (const float*)d_in[6];
    const float* att_edge = (const float*)d_in[7];
    const float* gat_bias = (const float*)d_in[8];
    const float* bias     = (const float*)d_in[9];
    float* out = (float*)d_out;

    // one-time resource creation (streams/events are resources, not work;
    // every call performs the identical kernel DAG)
    static cudaStream_t s_aux = 0;
    static cudaEvent_t  ev_fork = 0, ev_join = 0;
    if (s_aux == 0) {
        cudaStreamCreateWithFlags(&s_aux, cudaStreamNonBlocking);
        cudaEventCreateWithFlags(&ev_fork, cudaEventDisableTiming);
        cudaEventCreateWithFlags(&ev_join, cudaEventDisableTiming);
    }

    // fork: CSR-build chain on aux stream, GEMM path on main stream
    cudaEventRecord(ev_fork, 0);
    cudaStreamWaitEvent(s_aux, ev_fork, 0);

    k_init <<<(N_NODES + 255) / 256, 256, 0, s_aux>>>();
    k_count<<<(N_EDGES / 4 + 255) / 256, 256, 0, s_aux>>>(ei);
    k_scan1<<<N_SCAN_BLKS, 256, 0, s_aux>>>();
    k_scan2<<<1, 32, 0, s_aux>>>();
    k_scan3<<<(N_NODES + 255) / 256, 256, 0, s_aux>>>();
    cudaEventRecord(ev_join, s_aux);

    k_wpw  <<<33, 256>>>(W, W_edge, att_edge);
    k_gemm <<<(N_NODES + 127) / 128, 256>>>(x, att_src, att_dst);

    // join: edge scatter needs gemm (asrc/adst) + cursors + weff
    cudaStreamWaitEvent(0, ev_join, 0);
    k_edge_scatter<<<N_EDGES / 256, 256>>>(ei, ea);
    k_agg         <<<(N_NODES + 7) / 8, 256>>>(out, gat_bias, bias);
}